// round 1
// baseline (speedup 1.0000x reference)
#include <cuda_runtime.h>
#include <math.h>

#define BB 2
#define TT 2048
#define DMM 512
#define HH 8
#define DD 64
#define UU 3
#define BH (BB*HH)

// scratch (device globals; no allocation allowed)
__device__ float g_Q[BH*TT*DD];    // [b,h,t,d]
__device__ float g_K[BH*TT*DD];
__device__ float g_V[BH*TT*DD];
__device__ float g_kl[BH*TT];
__device__ int   g_top[BH*UU];
__device__ float g_or[BH*UU*DD];   // out_red

// ---------------------------------------------------------------------------
// Projection GEMM: P[b,h,t,d] = sum_c X[b*T+t, c] * W[h*64+d, c] + bias[h*64+d]
// M=4096, N=512, K=512. 64x64 tile, 256 threads, each 4x4.
// ---------------------------------------------------------------------------
__global__ void proj_kernel(const float* __restrict__ X,
                            const float* __restrict__ W,
                            const float* __restrict__ bias,
                            float* __restrict__ P) {
    __shared__ float As[16][68];
    __shared__ float Ws[16][68];
    const int tid = threadIdx.x;
    const int tx = tid % 16, ty = tid / 16;
    const int m0 = blockIdx.y * 64, n0 = blockIdx.x * 64;

    float acc[4][4];
#pragma unroll
    for (int i = 0; i < 4; i++)
#pragma unroll
        for (int j = 0; j < 4; j++) acc[i][j] = 0.f;

    const int lrow = tid / 4;          // 0..63
    const int lf   = tid % 4;          // 0..3 (float4 within 16-wide k tile)

    for (int k0 = 0; k0 < DMM; k0 += 16) {
        float4 va = *(const float4*)(X + (size_t)(m0 + lrow) * DMM + k0 + lf * 4);
        float4 vb = *(const float4*)(W + (size_t)(n0 + lrow) * DMM + k0 + lf * 4);
        As[lf*4+0][lrow] = va.x; As[lf*4+1][lrow] = va.y;
        As[lf*4+2][lrow] = va.z; As[lf*4+3][lrow] = va.w;
        Ws[lf*4+0][lrow] = vb.x; Ws[lf*4+1][lrow] = vb.y;
        Ws[lf*4+2][lrow] = vb.z; Ws[lf*4+3][lrow] = vb.w;
        __syncthreads();
#pragma unroll
        for (int kk = 0; kk < 16; kk++) {
            float4 a = *(const float4*)&As[kk][ty * 4];
            float4 b = *(const float4*)&Ws[kk][tx * 4];
            float av[4] = {a.x, a.y, a.z, a.w};
            float bv[4] = {b.x, b.y, b.z, b.w};
#pragma unroll
            for (int i = 0; i < 4; i++)
#pragma unroll
                for (int j = 0; j < 4; j++) acc[i][j] = fmaf(av[i], bv[j], acc[i][j]);
        }
        __syncthreads();
    }

#pragma unroll
    for (int i = 0; i < 4; i++) {
        int m = m0 + ty * 4 + i;
        int b = m / TT, t = m % TT;
#pragma unroll
        for (int j = 0; j < 4; j++) {
            int n = n0 + tx * 4 + j;
            int h = n / DD, d = n % DD;
            P[(((size_t)(b * HH + h)) * TT + t) * DD + d] = acc[i][j] + bias[n];
        }
    }
}

// ---------------------------------------------------------------------------
// Fused scores + online-softmax KL statistic.
// Block: (qtile of 64, bh). 256 threads (16x16), each 4 queries x 4 keys.
// kl_stat = sum_i p_i*(s_i - m) - log Z  (monotone-equal to reference KL)
// ---------------------------------------------------------------------------
__global__ void kl_kernel() {
    __shared__ float Qs[64][68];   // [d][q]
    __shared__ float Ks[64][68];   // [d][k]
    const int tid = threadIdx.x;
    const int tx = tid % 16, ty = tid / 16;
    const int bh = blockIdx.y;
    const int q0 = blockIdx.x * 64;
    const float* Qbase = g_Q + ((size_t)bh * TT + q0) * DD;
    const float* Kh    = g_K + (size_t)bh * TT * DD;

    // load Q tile once: Qs[d][q]
#pragma unroll
    for (int it = 0; it < 4; it++) {
        int q  = (tid / 16) + it * 16;
        int d0 = (tid % 16) * 4;
        float4 v = *(const float4*)(Qbase + (size_t)q * DD + d0);
        Qs[d0+0][q] = v.x; Qs[d0+1][q] = v.y; Qs[d0+2][q] = v.z; Qs[d0+3][q] = v.w;
    }

    float m[4], Z[4], Tc[4];
#pragma unroll
    for (int i = 0; i < 4; i++) { m[i] = -1e30f; Z[i] = 0.f; Tc[i] = 0.f; }

    for (int kt = 0; kt < TT / 64; kt++) {
        __syncthreads();
#pragma unroll
        for (int it = 0; it < 4; it++) {
            int k  = (tid / 16) + it * 16;
            int d0 = (tid % 16) * 4;
            float4 v = *(const float4*)(Kh + ((size_t)(kt * 64 + k)) * DD + d0);
            Ks[d0+0][k] = v.x; Ks[d0+1][k] = v.y; Ks[d0+2][k] = v.z; Ks[d0+3][k] = v.w;
        }
        __syncthreads();

        float c[4][4];
#pragma unroll
        for (int i = 0; i < 4; i++)
#pragma unroll
            for (int j = 0; j < 4; j++) c[i][j] = 0.f;

#pragma unroll
        for (int d = 0; d < 64; d++) {
            float4 a = *(const float4*)&Qs[d][ty * 4];
            float4 b = *(const float4*)&Ks[d][tx * 4];
            float av[4] = {a.x, a.y, a.z, a.w};
            float bv[4] = {b.x, b.y, b.z, b.w};
#pragma unroll
            for (int i = 0; i < 4; i++)
#pragma unroll
                for (int j = 0; j < 4; j++) c[i][j] = fmaf(av[i], bv[j], c[i][j]);
        }

        // online softmax/KL update for this thread's 4 keys per query
#pragma unroll
        for (int i = 0; i < 4; i++) {
            float v0 = c[i][0] * 0.125f, v1 = c[i][1] * 0.125f;
            float v2 = c[i][2] * 0.125f, v3 = c[i][3] * 0.125f;
            float tmax = fmaxf(fmaxf(v0, v1), fmaxf(v2, v3));
            float nm = fmaxf(m[i], tmax);
            float f = __expf(m[i] - nm);
            Tc[i] = f * (Tc[i] + Z[i] * (m[i] - nm));
            Z[i] *= f;
            float e0 = __expf(v0 - nm), e1 = __expf(v1 - nm);
            float e2 = __expf(v2 - nm), e3 = __expf(v3 - nm);
            Z[i]  += e0 + e1 + e2 + e3;
            Tc[i] += e0 * (v0 - nm) + e1 * (v1 - nm) + e2 * (v2 - nm) + e3 * (v3 - nm);
            m[i] = nm;
        }
    }

    // merge across the 16 tx-lanes (same ty group, aligned 16-lane subsets)
#pragma unroll
    for (int i = 0; i < 4; i++) {
#pragma unroll
        for (int off = 8; off > 0; off >>= 1) {
            float mo = __shfl_xor_sync(0xffffffffu, m[i],  off, 16);
            float zo = __shfl_xor_sync(0xffffffffu, Z[i],  off, 16);
            float to = __shfl_xor_sync(0xffffffffu, Tc[i], off, 16);
            float nm = fmaxf(m[i], mo);
            float f1 = __expf(m[i] - nm), f2 = __expf(mo - nm);
            Tc[i] = f1 * (Tc[i] + Z[i] * (m[i] - nm)) + f2 * (to + zo * (mo - nm));
            Z[i]  = Z[i] * f1 + zo * f2;
            m[i] = nm;
        }
    }
    if (tx == 0) {
#pragma unroll
        for (int i = 0; i < 4; i++) {
            float r = Tc[i] / Z[i] - logf(Z[i]);
            g_kl[(size_t)bh * TT + q0 + ty * 4 + i] = r;
        }
    }
}

// ---------------------------------------------------------------------------
// Top-3 per (b,h) by KL, jax top_k tie semantics (equal -> lower index first)
// ---------------------------------------------------------------------------
__global__ void top3_kernel() {
    const int bh = blockIdx.x;
    __shared__ float sv[256];
    __shared__ int   si[256];
    __shared__ int   chosen[UU];
    const float* kl = g_kl + (size_t)bh * TT;
    for (int p = 0; p < UU; p++) {
        float bv = -1e38f; int bi = TT;
        for (int q = threadIdx.x; q < TT; q += 256) {
            bool skip = false;
            for (int c = 0; c < p; c++) if (chosen[c] == q) skip = true;
            if (skip) continue;
            float v = kl[q];
            if (v > bv || (v == bv && q < bi)) { bv = v; bi = q; }
        }
        sv[threadIdx.x] = bv; si[threadIdx.x] = bi;
        __syncthreads();
        for (int s = 128; s > 0; s >>= 1) {
            if (threadIdx.x < s) {
                float ov = sv[threadIdx.x + s]; int oi = si[threadIdx.x + s];
                if (ov > sv[threadIdx.x] ||
                    (ov == sv[threadIdx.x] && oi < si[threadIdx.x])) {
                    sv[threadIdx.x] = ov; si[threadIdx.x] = oi;
                }
            }
            __syncthreads();
        }
        if (threadIdx.x == 0) { chosen[p] = si[0]; g_top[bh * UU + p] = si[0]; }
        __syncthreads();
    }
}

// ---------------------------------------------------------------------------
// Reduced attention for the 48 selected rows: softmax(clip(qk/8)) @ V
// One block per selected (bh, slot). 256 threads.
// ---------------------------------------------------------------------------
__global__ void redattn_kernel() {
    const int slot = blockIdx.x;         // 0..47
    const int bh = slot / UU;
    const int t = g_top[slot];
    __shared__ float qrow[64];
    __shared__ float sarr[TT];
    __shared__ float red[256];
    const int tid = threadIdx.x;

    if (tid < 64) qrow[tid] = g_Q[((size_t)bh * TT + t) * DD + tid];
    __syncthreads();

    for (int k = tid; k < TT; k += 256) {
        const float* kr = g_K + ((size_t)bh * TT + k) * DD;
        float s = 0.f;
#pragma unroll
        for (int d = 0; d < 64; d++) s = fmaf(qrow[d], kr[d], s);
        s *= 0.125f;
        if (!(s == s)) s = -10000.0f;              // nan_to_num
        s = fminf(fmaxf(s, -10000.0f), 10000.0f);  // clip
        sarr[k] = s;
    }
    __syncthreads();

    float lm = -1e30f;
    for (int k = tid; k < TT; k += 256) lm = fmaxf(lm, sarr[k]);
    red[tid] = lm; __syncthreads();
    for (int s = 128; s > 0; s >>= 1) {
        if (tid < s) red[tid] = fmaxf(red[tid], red[tid + s]);
        __syncthreads();
    }
    float mx = red[0]; __syncthreads();

    float lz = 0.f;
    for (int k = tid; k < TT; k += 256) {
        float e = expf(sarr[k] - mx);
        sarr[k] = e;
        lz += e;
    }
    red[tid] = lz; __syncthreads();
    for (int s = 128; s > 0; s >>= 1) {
        if (tid < s) red[tid] += red[tid + s];
        __syncthreads();
    }
    float Zs = red[0]; __syncthreads();

    const int d = tid % 64, g = tid / 64;
    float acc = 0.f;
    for (int k = g; k < TT; k += 4)
        acc = fmaf(sarr[k], g_V[((size_t)bh * TT + k) * DD + d], acc);
    red[tid] = acc; __syncthreads();
    if (tid < 64) {
        float o = (red[tid] + red[tid + 64] + red[tid + 128] + red[tid + 192]) / Zs;
        g_or[(size_t)slot * DD + tid] = o;
    }
}

// ---------------------------------------------------------------------------
// Output: init to bias, then sparse-project the 48 nonzero rows with Wo
// ---------------------------------------------------------------------------
__global__ void init_out_kernel(float* __restrict__ out, const float* __restrict__ bo) {
    int idx = blockIdx.x * 256 + threadIdx.x;
    if (idx < BB * TT * DMM) out[idx] = bo[idx % DMM];
}

__global__ void scatter_kernel(const float* __restrict__ Wo, float* __restrict__ out) {
    const int slot = blockIdx.x;
    const int bh = slot / UU;
    const int b = bh / HH, h = bh % HH;
    const int t = g_top[slot];
    __shared__ float orow[64];
    if (threadIdx.x < 64) orow[threadIdx.x] = g_or[(size_t)slot * DD + threadIdx.x];
    __syncthreads();
    for (int n = threadIdx.x; n < DMM; n += 256) {
        const float* wr = Wo + (size_t)n * DMM + h * DD;
        float acc = 0.f;
#pragma unroll
        for (int d = 0; d < 64; d++) acc = fmaf(orow[d], wr[d], acc);
        atomicAdd(&out[((size_t)b * TT + t) * DMM + n], acc);
    }
}

// ---------------------------------------------------------------------------
extern "C" void kernel_launch(void* const* d_in, const int* in_sizes, int n_in,
                              void* d_out, int out_size) {
    const float* query = (const float*)d_in[0];
    const float* key   = (const float*)d_in[1];
    const float* value = (const float*)d_in[2];
    const float* Wq = (const float*)d_in[3];
    const float* bq = (const float*)d_in[4];
    const float* Wk = (const float*)d_in[5];
    const float* bk = (const float*)d_in[6];
    const float* Wv = (const float*)d_in[7];
    const float* bv = (const float*)d_in[8];
    const float* Wo = (const float*)d_in[9];
    const float* bo = (const float*)d_in[10];
    float* out = (float*)d_out;

    float *Qp, *Kp, *Vp;
    cudaGetSymbolAddress((void**)&Qp, g_Q);
    cudaGetSymbolAddress((void**)&Kp, g_K);
    cudaGetSymbolAddress((void**)&Vp, g_V);

    dim3 pg(DMM / 64, (BB * TT) / 64);
    proj_kernel<<<pg, 256>>>(query, Wq, bq, Qp);
    proj_kernel<<<pg, 256>>>(key,   Wk, bk, Kp);
    proj_kernel<<<pg, 256>>>(value, Wv, bv, Vp);

    dim3 kg(TT / 64, BH);
    kl_kernel<<<kg, 256>>>();

    top3_kernel<<<BH, 256>>>();
    redattn_kernel<<<BH * UU, 256>>>();

    init_out_kernel<<<(BB * TT * DMM + 255) / 256, 256>>>(out, bo);
    scatter_kernel<<<BH * UU, 256>>>(Wo, out);
}

// round 2
// speedup vs baseline: 1.3527x; 1.3527x over previous
#include <cuda_runtime.h>
#include <math.h>

#define BB 2
#define TT 2048
#define DMM 512
#define HH 8
#define DD 64
#define UU 3
#define BH (BB*HH)

typedef unsigned long long u64;

// scratch (device globals; no allocation allowed)
__device__ float g_Q[BH*TT*DD];    // [b,h,t,d]
__device__ float g_K[BH*TT*DD];
__device__ float g_V[BH*TT*DD];
__device__ float g_kl[BH*TT];
__device__ int   g_top[BH*UU];
__device__ float g_or[BH*UU*DD];   // out_red

// ---------------------------------------------------------------------------
// f32x2 packed helpers (FFMA2 — only reachable via PTX)
// ---------------------------------------------------------------------------
__device__ __forceinline__ u64 splat2(float x) {
    u64 r;
    asm("mov.b64 %0, {%1, %1};" : "=l"(r) : "r"(__float_as_uint(x)));
    return r;
}
__device__ __forceinline__ void fma2(u64 &d, u64 a, u64 b) {
    asm("fma.rn.f32x2 %0, %1, %2, %0;" : "+l"(d) : "l"(a), "l"(b));
}
__device__ __forceinline__ float2 unpack2(u64 v) {
    unsigned lo, hi;
    asm("mov.b64 {%0, %1}, %2;" : "=r"(lo), "=r"(hi) : "l"(v));
    return make_float2(__uint_as_float(lo), __uint_as_float(hi));
}

#define PSTR 132   // smem row stride in floats (16B-aligned rows)

// ---------------------------------------------------------------------------
// Fused QKV projection: grid (N/128, M/128, 3). 256 thr, 8x8/thread, f32x2.
// P[b,h,t,d] = sum_c X[b*T+t, c] * W[h*64+d, c] + bias[...]
// ---------------------------------------------------------------------------
__global__ __launch_bounds__(256) void proj_kernel(
    const float* __restrict__ X0, const float* __restrict__ X1, const float* __restrict__ X2,
    const float* __restrict__ W0, const float* __restrict__ W1, const float* __restrict__ W2,
    const float* __restrict__ B0, const float* __restrict__ B1, const float* __restrict__ B2,
    float* __restrict__ P0, float* __restrict__ P1, float* __restrict__ P2)
{
    __shared__ float As[16][PSTR];
    __shared__ float Ws[16][PSTR];
    const int z = blockIdx.z;
    const float* X = (z == 0) ? X0 : (z == 1) ? X1 : X2;
    const float* W = (z == 0) ? W0 : (z == 1) ? W1 : W2;
    const float* Bv = (z == 0) ? B0 : (z == 1) ? B1 : B2;
    float*       P = (z == 0) ? P0 : (z == 1) ? P1 : P2;

    const int tid = threadIdx.x;
    const int tx = tid % 16, ty = tid / 16;
    const int n0 = blockIdx.x * 128, m0 = blockIdx.y * 128;
    const int lr = tid / 2, lh = tid % 2;   // loader: row 0..127, k-half

    u64 acc[8][4];
#pragma unroll
    for (int i = 0; i < 8; i++)
#pragma unroll
        for (int j = 0; j < 4; j++) acc[i][j] = 0ull;

    for (int k0 = 0; k0 < DMM; k0 += 16) {
        // prefetch to regs (overlaps previous tile's compute)
        const float* xs = X + (size_t)(m0 + lr) * DMM + k0 + lh * 8;
        const float* ws = W + (size_t)(n0 + lr) * DMM + k0 + lh * 8;
        float4 xa = *(const float4*)(xs);
        float4 xb = *(const float4*)(xs + 4);
        float4 wa = *(const float4*)(ws);
        float4 wb = *(const float4*)(ws + 4);
        __syncthreads();
        As[lh*8+0][lr] = xa.x; As[lh*8+1][lr] = xa.y; As[lh*8+2][lr] = xa.z; As[lh*8+3][lr] = xa.w;
        As[lh*8+4][lr] = xb.x; As[lh*8+5][lr] = xb.y; As[lh*8+6][lr] = xb.z; As[lh*8+7][lr] = xb.w;
        Ws[lh*8+0][lr] = wa.x; Ws[lh*8+1][lr] = wa.y; Ws[lh*8+2][lr] = wa.z; Ws[lh*8+3][lr] = wa.w;
        Ws[lh*8+4][lr] = wb.x; Ws[lh*8+5][lr] = wb.y; Ws[lh*8+6][lr] = wb.z; Ws[lh*8+7][lr] = wb.w;
        __syncthreads();

#pragma unroll
        for (int kk = 0; kk < 16; kk++) {
            float4 qa = *(const float4*)&As[kk][ty * 8];
            float4 qb = *(const float4*)&As[kk][ty * 8 + 4];
            ulonglong2 kb0 = *(const ulonglong2*)&Ws[kk][tx * 4];
            ulonglong2 kb1 = *(const ulonglong2*)&Ws[kk][64 + tx * 4];
            u64 s[8];
            s[0] = splat2(qa.x); s[1] = splat2(qa.y); s[2] = splat2(qa.z); s[3] = splat2(qa.w);
            s[4] = splat2(qb.x); s[5] = splat2(qb.y); s[6] = splat2(qb.z); s[7] = splat2(qb.w);
#pragma unroll
            for (int i = 0; i < 8; i++) {
                fma2(acc[i][0], s[i], kb0.x);
                fma2(acc[i][1], s[i], kb0.y);
                fma2(acc[i][2], s[i], kb1.x);
                fma2(acc[i][3], s[i], kb1.y);
            }
        }
    }

#pragma unroll
    for (int i = 0; i < 8; i++) {
        int m = m0 + ty * 8 + i;
        int b = m / TT, t = m % TT;
#pragma unroll
        for (int c = 0; c < 2; c++) {
            int nb = n0 + c * 64 + tx * 4;
            int h = nb / DD, d = nb % DD;
            float4 bias = *(const float4*)(Bv + nb);
            float2 p0 = unpack2(acc[i][c * 2]);
            float2 p1 = unpack2(acc[i][c * 2 + 1]);
            float4 o = make_float4(p0.x + bias.x, p0.y + bias.y, p1.x + bias.z, p1.y + bias.w);
            *(float4*)&P[(((size_t)(b * HH + h)) * TT + t) * DD + d] = o;
        }
    }
}

// ---------------------------------------------------------------------------
// Fused scores + online-softmax KL statistic.
// grid (T/128, BH), 256 thr, 8q x 8k per thread, f32x2, dynamic smem.
// kl_stat = sum p*(s-m) - logZ  (rank-equal to reference KL)
// ---------------------------------------------------------------------------
__global__ __launch_bounds__(256) void kl_kernel() {
    extern __shared__ float sm[];
    float (*Qs)[PSTR] = (float(*)[PSTR])sm;              // [d][q]
    float (*Ks)[PSTR] = (float(*)[PSTR])(sm + 64 * PSTR); // [d][k]

    const int tid = threadIdx.x;
    const int tx = tid % 16, ty = tid / 16;
    const int bh = blockIdx.y;
    const int q0 = blockIdx.x * 128;
    const float* Qb = g_Q + ((size_t)bh * TT + q0) * DD;
    const float* Kh = g_K + (size_t)bh * TT * DD;
    const int lr = tid / 2, lh = tid % 2;   // loader: row, d-half (32 d)

    // load Q tile [128 x 64] transposed -> Qs[d][q]
    {
        const float* src = Qb + (size_t)lr * DD + lh * 32;
#pragma unroll
        for (int f = 0; f < 8; f++) {
            float4 v = *(const float4*)(src + f * 4);
            Qs[lh*32 + f*4 + 0][lr] = v.x;
            Qs[lh*32 + f*4 + 1][lr] = v.y;
            Qs[lh*32 + f*4 + 2][lr] = v.z;
            Qs[lh*32 + f*4 + 3][lr] = v.w;
        }
    }

    float m[8], Z[8], Tc[8];
#pragma unroll
    for (int i = 0; i < 8; i++) { m[i] = -1e30f; Z[i] = 0.f; Tc[i] = 0.f; }

    for (int kt = 0; kt < TT / 128; kt++) {
        const float* src = Kh + ((size_t)(kt * 128 + lr)) * DD + lh * 32;
        float4 kv[8];
#pragma unroll
        for (int f = 0; f < 8; f++) kv[f] = *(const float4*)(src + f * 4);
        __syncthreads();
#pragma unroll
        for (int f = 0; f < 8; f++) {
            Ks[lh*32 + f*4 + 0][lr] = kv[f].x;
            Ks[lh*32 + f*4 + 1][lr] = kv[f].y;
            Ks[lh*32 + f*4 + 2][lr] = kv[f].z;
            Ks[lh*32 + f*4 + 3][lr] = kv[f].w;
        }
        __syncthreads();

        u64 acc[8][4];
#pragma unroll
        for (int i = 0; i < 8; i++)
#pragma unroll
            for (int j = 0; j < 4; j++) acc[i][j] = 0ull;

#pragma unroll
        for (int d = 0; d < 64; d++) {
            float4 qa = *(const float4*)&Qs[d][ty * 8];
            float4 qb = *(const float4*)&Qs[d][ty * 8 + 4];
            ulonglong2 kb0 = *(const ulonglong2*)&Ks[d][tx * 4];
            ulonglong2 kb1 = *(const ulonglong2*)&Ks[d][64 + tx * 4];
            u64 s[8];
            s[0] = splat2(qa.x); s[1] = splat2(qa.y); s[2] = splat2(qa.z); s[3] = splat2(qa.w);
            s[4] = splat2(qb.x); s[5] = splat2(qb.y); s[6] = splat2(qb.z); s[7] = splat2(qb.w);
#pragma unroll
            for (int i = 0; i < 8; i++) {
                fma2(acc[i][0], s[i], kb0.x);
                fma2(acc[i][1], s[i], kb0.y);
                fma2(acc[i][2], s[i], kb1.x);
                fma2(acc[i][3], s[i], kb1.y);
            }
        }

        // online softmax/KL update: 8 keys per query
#pragma unroll
        for (int i = 0; i < 8; i++) {
            float v[8];
            float2 a0 = unpack2(acc[i][0]), a1 = unpack2(acc[i][1]);
            float2 a2 = unpack2(acc[i][2]), a3 = unpack2(acc[i][3]);
            v[0] = a0.x * 0.125f; v[1] = a0.y * 0.125f;
            v[2] = a1.x * 0.125f; v[3] = a1.y * 0.125f;
            v[4] = a2.x * 0.125f; v[5] = a2.y * 0.125f;
            v[6] = a3.x * 0.125f; v[7] = a3.y * 0.125f;
            float tmax = v[0];
#pragma unroll
            for (int j = 1; j < 8; j++) tmax = fmaxf(tmax, v[j]);
            float nm = fmaxf(m[i], tmax);
            float f = __expf(m[i] - nm);
            Tc[i] = f * (Tc[i] + Z[i] * (m[i] - nm));
            Z[i] *= f;
#pragma unroll
            for (int j = 0; j < 8; j++) {
                float e = __expf(v[j] - nm);
                Z[i] += e;
                Tc[i] += e * (v[j] - nm);
            }
            m[i] = nm;
        }
    }

    // merge across the 16 tx-lanes
#pragma unroll
    for (int i = 0; i < 8; i++) {
#pragma unroll
        for (int off = 8; off > 0; off >>= 1) {
            float mo = __shfl_xor_sync(0xffffffffu, m[i],  off, 16);
            float zo = __shfl_xor_sync(0xffffffffu, Z[i],  off, 16);
            float to = __shfl_xor_sync(0xffffffffu, Tc[i], off, 16);
            float nm = fmaxf(m[i], mo);
            float f1 = __expf(m[i] - nm), f2 = __expf(mo - nm);
            Tc[i] = f1 * (Tc[i] + Z[i] * (m[i] - nm)) + f2 * (to + zo * (mo - nm));
            Z[i]  = Z[i] * f1 + zo * f2;
            m[i] = nm;
        }
    }
    if (tx == 0) {
#pragma unroll
        for (int i = 0; i < 8; i++) {
            float r = Tc[i] / Z[i] - logf(Z[i]);
            g_kl[(size_t)bh * TT + q0 + ty * 8 + i] = r;
        }
    }
}

// ---------------------------------------------------------------------------
// Top-3 per (b,h) by KL, jax top_k tie semantics (equal -> lower index first)
// ---------------------------------------------------------------------------
__global__ void top3_kernel() {
    const int bh = blockIdx.x;
    __shared__ float sv[256];
    __shared__ int   si[256];
    __shared__ int   chosen[UU];
    const float* kl = g_kl + (size_t)bh * TT;
    for (int p = 0; p < UU; p++) {
        float bv = -1e38f; int bi = TT;
        for (int q = threadIdx.x; q < TT; q += 256) {
            bool skip = false;
            for (int c = 0; c < p; c++) if (chosen[c] == q) skip = true;
            if (skip) continue;
            float v = kl[q];
            if (v > bv || (v == bv && q < bi)) { bv = v; bi = q; }
        }
        sv[threadIdx.x] = bv; si[threadIdx.x] = bi;
        __syncthreads();
        for (int s = 128; s > 0; s >>= 1) {
            if (threadIdx.x < s) {
                float ov = sv[threadIdx.x + s]; int oi = si[threadIdx.x + s];
                if (ov > sv[threadIdx.x] ||
                    (ov == sv[threadIdx.x] && oi < si[threadIdx.x])) {
                    sv[threadIdx.x] = ov; si[threadIdx.x] = oi;
                }
            }
            __syncthreads();
        }
        if (threadIdx.x == 0) { chosen[p] = si[0]; g_top[bh * UU + p] = si[0]; }
        __syncthreads();
    }
}

// ---------------------------------------------------------------------------
// Reduced attention for the 48 selected rows: softmax(clip(qk/8)) @ V
// ---------------------------------------------------------------------------
__global__ void redattn_kernel() {
    const int slot = blockIdx.x;         // 0..47
    const int bh = slot / UU;
    const int t = g_top[slot];
    __shared__ float qrow[64];
    __shared__ float sarr[TT];
    __shared__ float red[256];
    const int tid = threadIdx.x;

    if (tid < 64) qrow[tid] = g_Q[((size_t)bh * TT + t) * DD + tid];
    __syncthreads();

    for (int k = tid; k < TT; k += 256) {
        const float* kr = g_K + ((size_t)bh * TT + k) * DD;
        float s = 0.f;
#pragma unroll
        for (int d = 0; d < 64; d++) s = fmaf(qrow[d], kr[d], s);
        s *= 0.125f;
        if (!(s == s)) s = -10000.0f;
        s = fminf(fmaxf(s, -10000.0f), 10000.0f);
        sarr[k] = s;
    }
    __syncthreads();

    float lm = -1e30f;
    for (int k = tid; k < TT; k += 256) lm = fmaxf(lm, sarr[k]);
    red[tid] = lm; __syncthreads();
    for (int s = 128; s > 0; s >>= 1) {
        if (tid < s) red[tid] = fmaxf(red[tid], red[tid + s]);
        __syncthreads();
    }
    float mx = red[0]; __syncthreads();

    float lz = 0.f;
    for (int k = tid; k < TT; k += 256) {
        float e = expf(sarr[k] - mx);
        sarr[k] = e;
        lz += e;
    }
    red[tid] = lz; __syncthreads();
    for (int s = 128; s > 0; s >>= 1) {
        if (tid < s) red[tid] += red[tid + s];
        __syncthreads();
    }
    float Zs = red[0]; __syncthreads();

    const int d = tid % 64, g = tid / 64;
    float acc = 0.f;
    for (int k = g; k < TT; k += 4)
        acc = fmaf(sarr[k], g_V[((size_t)bh * TT + k) * DD + d], acc);
    red[tid] = acc; __syncthreads();
    if (tid < 64) {
        float o = (red[tid] + red[tid + 64] + red[tid + 128] + red[tid + 192]) / Zs;
        g_or[(size_t)slot * DD + tid] = o;
    }
}

// ---------------------------------------------------------------------------
// Output: init to bias, then sparse-project the 48 nonzero rows with Wo
// ---------------------------------------------------------------------------
__global__ void init_out_kernel(float* __restrict__ out, const float* __restrict__ bo) {
    int idx = blockIdx.x * 256 + threadIdx.x;
    if (idx < BB * TT * DMM) out[idx] = bo[idx % DMM];
}

__global__ void scatter_kernel(const float* __restrict__ Wo, float* __restrict__ out) {
    const int slot = blockIdx.x;
    const int bh = slot / UU;
    const int b = bh / HH, h = bh % HH;
    const int t = g_top[slot];
    __shared__ float orow[64];
    if (threadIdx.x < 64) orow[threadIdx.x] = g_or[(size_t)slot * DD + threadIdx.x];
    __syncthreads();
    for (int n = threadIdx.x; n < DMM; n += 256) {
        const float* wr = Wo + (size_t)n * DMM + h * DD;
        float acc = 0.f;
#pragma unroll
        for (int d = 0; d < 64; d++) acc = fmaf(orow[d], wr[d], acc);
        atomicAdd(&out[((size_t)b * TT + t) * DMM + n], acc);
    }
}

// ---------------------------------------------------------------------------
extern "C" void kernel_launch(void* const* d_in, const int* in_sizes, int n_in,
                              void* d_out, int out_size) {
    const float* query = (const float*)d_in[0];
    const float* key   = (const float*)d_in[1];
    const float* value = (const float*)d_in[2];
    const float* Wq = (const float*)d_in[3];
    const float* bq = (const float*)d_in[4];
    const float* Wk = (const float*)d_in[5];
    const float* bk = (const float*)d_in[6];
    const float* Wv = (const float*)d_in[7];
    const float* bv = (const float*)d_in[8];
    const float* Wo = (const float*)d_in[9];
    const float* bo = (const float*)d_in[10];
    float* out = (float*)d_out;

    float *Qp, *Kp, *Vp;
    cudaGetSymbolAddress((void**)&Qp, g_Q);
    cudaGetSymbolAddress((void**)&Kp, g_K);
    cudaGetSymbolAddress((void**)&Vp, g_V);

    const int kl_smem = 2 * 64 * PSTR * sizeof(float);  // 67584 B
    cudaFuncSetAttribute(kl_kernel, cudaFuncAttributeMaxDynamicSharedMemorySize, kl_smem);

    dim3 pg(DMM / 128, (BB * TT) / 128, 3);
    proj_kernel<<<pg, 256>>>(query, key, value,
                             Wq, Wk, Wv,
                             bq, bk, bv,
                             Qp, Kp, Vp);

    dim3 kg(TT / 128, BH);
    kl_kernel<<<kg, 256, kl_smem>>>();

    top3_kernel<<<BH, 256>>>();
    redattn_kernel<<<BH * UU, 256>>>();

    init_out_kernel<<<(BB * TT * DMM + 255) / 256, 256>>>(out, bo);
    scatter_kernel<<<BH * UU, 256>>>(Wo, out);
}

// round 5
// speedup vs baseline: 1.6995x; 1.2563x over previous
#include <cuda_runtime.h>
#include <cuda_bf16.h>
#include <math.h>
#include <stdint.h>

#define BB 2
#define TT 2048
#define DMM 512
#define HH 8
#define DD 64
#define UU 3
#define BH (BB*HH)

typedef unsigned long long u64;

// fp32 scratch
__device__ float g_Q[BH*TT*DD];    // [b,h,t,d]
__device__ float g_K[BH*TT*DD];
__device__ float g_V[BH*TT*DD];
__device__ float g_kl[BH*TT];
__device__ int   g_top[BH*UU];
__device__ float g_or[BH*UU*DD];
__device__ float g_part[BH*UU*8*68];

// bf16 hi/lo packed (bf16x2 per uint), row-major
__device__ unsigned g_Xh[3*4096*256];   // [z][m][k/2]
__device__ unsigned g_Xl[3*4096*256];
__device__ unsigned g_Wh[3*512*256];    // [z][n][k/2]
__device__ unsigned g_Wl[3*512*256];
__device__ unsigned g_Qh[BH*TT*32];     // [bh][t][d/2]  (scaled by 1/8)
__device__ unsigned g_Ql[BH*TT*32];
__device__ unsigned g_Kh[BH*TT*32];
__device__ unsigned g_Kl[BH*TT*32];

// ---------------------------------------------------------------------------
__device__ __forceinline__ uint32_t smem_u32(const void* p) {
    uint32_t a;
    asm("{ .reg .u64 t; cvta.to.shared.u64 t, %1; cvt.u32.u64 %0, t; }" : "=r"(a) : "l"(p));
    return a;
}

__device__ __forceinline__ void ldsm4(uint32_t addr, uint32_t& r0, uint32_t& r1,
                                      uint32_t& r2, uint32_t& r3) {
    asm volatile("ldmatrix.sync.aligned.m8n8.x4.shared.b16 {%0,%1,%2,%3}, [%4];"
                 : "=r"(r0), "=r"(r1), "=r"(r2), "=r"(r3) : "r"(addr));
}

__device__ __forceinline__ void mma_bf16(float& c0, float& c1, float& c2, float& c3,
                                         uint32_t a0, uint32_t a1, uint32_t a2, uint32_t a3,
                                         uint32_t b0, uint32_t b1) {
    asm("mma.sync.aligned.m16n8k16.row.col.f32.bf16.bf16.f32 "
        "{%0,%1,%2,%3}, {%4,%5,%6,%7}, {%8,%9}, {%0,%1,%2,%3};"
        : "+f"(c0), "+f"(c1), "+f"(c2), "+f"(c3)
        : "r"(a0), "r"(a1), "r"(a2), "r"(a3), "r"(b0), "r"(b1));
}

// ---------------------------------------------------------------------------
// fp32 -> bf16 hi/lo split (8 consecutive elements -> 4 uints hi + 4 lo)
// ---------------------------------------------------------------------------
__device__ __forceinline__ void split8(const float* src, uint4& hi, uint4& lo) {
    float4 a = *(const float4*)src;
    float4 b = *(const float4*)(src + 4);
    float v[8] = {a.x, a.y, a.z, a.w, b.x, b.y, b.z, b.w};
    unsigned h16[8], l16[8];
#pragma unroll
    for (int i = 0; i < 8; i++) {
        __nv_bfloat16 h = __float2bfloat16_rn(v[i]);
        float r = v[i] - __bfloat162float(h);
        __nv_bfloat16 l = __float2bfloat16_rn(r);
        h16[i] = __bfloat16_as_ushort(h);
        l16[i] = __bfloat16_as_ushort(l);
    }
    hi = make_uint4(h16[0] | (h16[1] << 16), h16[2] | (h16[3] << 16),
                    h16[4] | (h16[5] << 16), h16[6] | (h16[7] << 16));
    lo = make_uint4(l16[0] | (l16[1] << 16), l16[2] | (l16[3] << 16),
                    l16[4] | (l16[5] << 16), l16[6] | (l16[7] << 16));
}

__global__ __launch_bounds__(256) void convx_kernel(
    const float* __restrict__ X0, const float* __restrict__ X1, const float* __restrict__ X2)
{
    const int z = blockIdx.y;
    const float* X = (z == 0) ? X0 : (z == 1) ? X1 : X2;
    int idx = blockIdx.x * 256 + threadIdx.x;        // over 4096*64
    uint4 hi, lo;
    split8(X + (size_t)idx * 8, hi, lo);
    size_t di = (size_t)z * 4096 * 64 + idx;
    ((uint4*)g_Xh)[di] = hi;
    ((uint4*)g_Xl)[di] = lo;
}

__global__ __launch_bounds__(256) void convw_kernel(
    const float* __restrict__ W0, const float* __restrict__ W1, const float* __restrict__ W2)
{
    const int z = blockIdx.y;
    const float* W = (z == 0) ? W0 : (z == 1) ? W1 : W2;
    int idx = blockIdx.x * 256 + threadIdx.x;        // over 512*64
    uint4 hi, lo;
    split8(W + (size_t)idx * 8, hi, lo);
    size_t di = (size_t)z * 512 * 64 + idx;
    ((uint4*)g_Wh)[di] = hi;
    ((uint4*)g_Wl)[di] = lo;
}

// ---------------------------------------------------------------------------
// Projection via mma.sync bf16 3-term split.
// grid (nt=4, mt=32, z=3), 256 thr = 8 warps x 16 rows. Block tile 128x128.
// ---------------------------------------------------------------------------
__global__ __launch_bounds__(256) void proj_mma_kernel(
    const float* __restrict__ B0, const float* __restrict__ B1, const float* __restrict__ B2,
    float* __restrict__ P0, float* __restrict__ P1, float* __restrict__ P2)
{
    extern __shared__ char dsm[];
    char* sbase = (char*)(((uintptr_t)dsm + 1023u) & ~(uintptr_t)1023u);
    uint4* sXh = (uint4*)sbase;              // 128 rows x 128B
    uint4* sXl = sXh + 1024;
    uint4* sWh = sXh + 2048;
    uint4* sWl = sXh + 3072;
    const uint32_t sb = smem_u32(sbase);

    const int z = blockIdx.z;
    const float* Bv = (z == 0) ? B0 : (z == 1) ? B1 : B2;
    float*       P = (z == 0) ? P0 : (z == 1) ? P1 : P2;
    const int nt = blockIdx.x, mt = blockIdx.y;
    const int tid = threadIdx.x;
    const int wid = tid >> 5, lane = tid & 31;
    const int r = lane & 7, g = lane >> 3;
    const int wrow0 = wid * 16;
    const int m0 = mt * 128, n0 = nt * 128;

    float acc[16][4];
#pragma unroll
    for (int i = 0; i < 16; i++)
#pragma unroll
        for (int j = 0; j < 4; j++) acc[i][j] = 0.f;

    // per-lane ldmatrix smem byte offsets (pre-swizzled row bases)
    const int rowA = wrow0 + r + (g & 1) * 8;
    const uint32_t abase = sb + rowA * 128;
    const int gbA = g >> 1;   // A chunk-half selector
    const int gbB = g & 1;    // B chunk-half selector
    const int rowBoff = r + ((g >> 1) & 1) * 8;

    for (int kc = 0; kc < 8; kc++) {
        __syncthreads();
        // fill 4 tiles: 1024 uint4 each, 256 threads -> 4 per tile
#pragma unroll
        for (int j = 0; j < 4; j++) {
            int i = tid + j * 256;
            int row = i >> 3, c = i & 7;
            uint32_t boff = row * 128 + c * 16;
            uint32_t sw = (boff ^ ((boff >> 3) & 0x70)) >> 4;
            size_t sx = (size_t)(z * 4096 + m0 + row) * 64 + kc * 8 + c;
            size_t swi = (size_t)(z * 512 + n0 + row) * 64 + kc * 8 + c;
            sXh[sw] = ((const uint4*)g_Xh)[sx];
            sXl[sw] = ((const uint4*)g_Xl)[sx];
            sWh[sw] = ((const uint4*)g_Wh)[swi];
            sWl[sw] = ((const uint4*)g_Wl)[swi];
        }
        __syncthreads();

#pragma unroll
        for (int ks = 0; ks < 4; ks++) {
            uint32_t aoffs = ((uint32_t)((ks * 2 + gbA) * 16)) ^ (uint32_t)(r * 16);
            uint32_t ah0, ah1, ah2, ah3, al0, al1, al2, al3;
            ldsm4(abase + aoffs, ah0, ah1, ah2, ah3);
            ldsm4(abase + 16384 + aoffs, al0, al1, al2, al3);
            uint32_t boffs = ((uint32_t)((ks * 2 + gbB) * 16)) ^ (uint32_t)(r * 16);
#pragma unroll
            for (int np = 0; np < 8; np++) {
                uint32_t bbase = sb + 32768 + (np * 16 + rowBoff) * 128 + boffs;
                uint32_t bh0, bh1, bh2, bh3, bl0, bl1, bl2, bl3;
                ldsm4(bbase, bh0, bh1, bh2, bh3);
                ldsm4(bbase + 16384, bl0, bl1, bl2, bl3);
                int f0 = np * 2, f1 = np * 2 + 1;
                mma_bf16(acc[f0][0], acc[f0][1], acc[f0][2], acc[f0][3],
                         ah0, ah1, ah2, ah3, bh0, bh1);
                mma_bf16(acc[f1][0], acc[f1][1], acc[f1][2], acc[f1][3],
                         ah0, ah1, ah2, ah3, bh2, bh3);
                mma_bf16(acc[f0][0], acc[f0][1], acc[f0][2], acc[f0][3],
                         ah0, ah1, ah2, ah3, bl0, bl1);
                mma_bf16(acc[f1][0], acc[f1][1], acc[f1][2], acc[f1][3],
                         ah0, ah1, ah2, ah3, bl2, bl3);
                mma_bf16(acc[f0][0], acc[f0][1], acc[f0][2], acc[f0][3],
                         al0, al1, al2, al3, bh0, bh1);
                mma_bf16(acc[f1][0], acc[f1][1], acc[f1][2], acc[f1][3],
                         al0, al1, al2, al3, bh2, bh3);
            }
        }
    }

    // epilogue
    const int mrow0 = m0 + wrow0 + (lane >> 2);
#pragma unroll
    for (int half = 0; half < 2; half++) {
        int m = mrow0 + half * 8;
        int b = m >> 11, t = m & 2047;
#pragma unroll
        for (int nf = 0; nf < 16; nf++) {
            int n = n0 + nf * 8 + 2 * (lane & 3);
            int h = n >> 6, d = n & 63;
            float2 bias = *(const float2*)(Bv + n);
            float v0 = acc[nf][half * 2] + bias.x;
            float v1 = acc[nf][half * 2 + 1] + bias.y;
            size_t po = (((size_t)(b * HH + h)) * TT + t) * DD + d;
            *(float2*)&P[po] = make_float2(v0, v1);
            if (z < 2) {
                float s0 = v0, s1 = v1;
                if (z == 0) { s0 *= 0.125f; s1 *= 0.125f; }
                __nv_bfloat16 h0 = __float2bfloat16_rn(s0);
                __nv_bfloat16 h1 = __float2bfloat16_rn(s1);
                float l0 = s0 - __bfloat162float(h0);
                float l1 = s1 - __bfloat162float(h1);
                unsigned hp = (unsigned)__bfloat16_as_ushort(h0) |
                              ((unsigned)__bfloat16_as_ushort(h1) << 16);
                unsigned lp = (unsigned)__bfloat16_as_ushort(__float2bfloat16_rn(l0)) |
                              ((unsigned)__bfloat16_as_ushort(__float2bfloat16_rn(l1)) << 16);
                size_t qo = (((size_t)(b * HH + h)) * TT + t) * 32 + (d >> 1);
                if (z == 0) { g_Qh[qo] = hp; g_Ql[qo] = lp; }
                else        { g_Kh[qo] = hp; g_Kl[qo] = lp; }
            }
        }
    }
}

// ---------------------------------------------------------------------------
// KL statistic via mma.sync: S = Qs·K^T (scale folded into Qs), online softmax.
// grid (qt=16, bh=16), 256 thr = 8 warps x 16 q-rows; warp covers all 128 keys/tile.
// ---------------------------------------------------------------------------
__global__ __launch_bounds__(256) void kl_mma_kernel() {
    extern __shared__ char dsm[];
    char* sbase = (char*)(((uintptr_t)dsm + 1023u) & ~(uintptr_t)1023u);
    uint4* sQh = (uint4*)sbase;
    uint4* sQl = sQh + 1024;
    uint4* sKh = sQh + 2048;
    uint4* sKl = sQh + 3072;
    const uint32_t sb = smem_u32(sbase);

    const int tid = threadIdx.x;
    const int wid = tid >> 5, lane = tid & 31;
    const int r = lane & 7, g = lane >> 3;
    const int wrow0 = wid * 16;
    const int bh = blockIdx.y;
    const int q0 = blockIdx.x * 128;

    // fill Q tiles (hi/lo): 1024 uint4 each, 4 per thread
#pragma unroll
    for (int j = 0; j < 4; j++) {
        int i = tid + j * 256;
        int row = i >> 3, c = i & 7;
        uint32_t boff = row * 128 + c * 16;
        uint32_t sw = (boff ^ ((boff >> 3) & 0x70)) >> 4;
        size_t sidx = (size_t)(bh * TT + q0 + row) * 8 + c;
        sQh[sw] = ((const uint4*)g_Qh)[sidx];
        sQl[sw] = ((const uint4*)g_Ql)[sidx];
    }
    __syncthreads();

    // hoist Q fragments for all 4 k-steps
    uint32_t Ah[4][4], Al[4][4];
    {
        const int rowA = wrow0 + r + (g & 1) * 8;
        const uint32_t abase = sb + rowA * 128;
        const int gbA = g >> 1;
#pragma unroll
        for (int ks = 0; ks < 4; ks++) {
            uint32_t aoffs = ((uint32_t)((ks * 2 + gbA) * 16)) ^ (uint32_t)(r * 16);
            ldsm4(abase + aoffs, Ah[ks][0], Ah[ks][1], Ah[ks][2], Ah[ks][3]);
            ldsm4(abase + 16384 + aoffs, Al[ks][0], Al[ks][1], Al[ks][2], Al[ks][3]);
        }
    }

    float mst[2] = {-1e30f, -1e30f}, Zc[2] = {0.f, 0.f}, Tc[2] = {0.f, 0.f};
    const int gbB = g & 1;
    const int rowBoff = r + ((g >> 1) & 1) * 8;

    for (int kt = 0; kt < TT / 128; kt++) {
        __syncthreads();
#pragma unroll
        for (int j = 0; j < 4; j++) {
            int i = tid + j * 256;
            int row = i >> 3, c = i & 7;
            uint32_t boff = row * 128 + c * 16;
            uint32_t sw = (boff ^ ((boff >> 3) & 0x70)) >> 4;
            size_t sidx = (size_t)(bh * TT + kt * 128 + row) * 8 + c;
            sKh[sw] = ((const uint4*)g_Kh)[sidx];
            sKl[sw] = ((const uint4*)g_Kl)[sidx];
        }
        __syncthreads();

        float acc[16][4];
#pragma unroll
        for (int i = 0; i < 16; i++)
#pragma unroll
            for (int j = 0; j < 4; j++) acc[i][j] = 0.f;

#pragma unroll
        for (int ks = 0; ks < 4; ks++) {
            uint32_t boffs = ((uint32_t)((ks * 2 + gbB) * 16)) ^ (uint32_t)(r * 16);
#pragma unroll
            for (int np = 0; np < 8; np++) {
                uint32_t bbase = sb + 32768 + (np * 16 + rowBoff) * 128 + boffs;
                uint32_t bh0, bh1, bh2, bh3, bl0, bl1, bl2, bl3;
                ldsm4(bbase, bh0, bh1, bh2, bh3);
                ldsm4(bbase + 16384, bl0, bl1, bl2, bl3);
                int f0 = np * 2, f1 = np * 2 + 1;
                mma_bf16(acc[f0][0], acc[f0][1], acc[f0][2], acc[f0][3],
                         Ah[ks][0], Ah[ks][1], Ah[ks][2], Ah[ks][3], bh0, bh1);
                mma_bf16(acc[f1][0], acc[f1][1], acc[f1][2], acc[f1][3],
                         Ah[ks][0], Ah[ks][1], Ah[ks][2], Ah[ks][3], bh2, bh3);
                mma_bf16(acc[f0][0], acc[f0][1], acc[f0][2], acc[f0][3],
                         Ah[ks][0], Ah[ks][1], Ah[ks][2], Ah[ks][3], bl0, bl1);
                mma_bf16(acc[f1][0], acc[f1][1], acc[f1][2], acc[f1][3],
                         Ah[ks][0], Ah[ks][1], Ah[ks][2], Ah[ks][3], bl2, bl3);
                mma_bf16(acc[f0][0], acc[f0][1], acc[f0][2], acc[f0][3],
                         Al[ks][0], Al[ks][1], Al[ks][2], Al[ks][3], bh0, bh1);
                mma_bf16(acc[f1][0], acc[f1][1], acc[f1][2], acc[f1][3],
                         Al[ks][0], Al[ks][1], Al[ks][2], Al[ks][3], bh2, bh3);
            }
        }

        // online softmax/KL update (2 row-halves per thread)
#pragma unroll
        for (int h2 = 0; h2 < 2; h2++) {
            float tmax = -1e30f;
#pragma unroll
            for (int nf = 0; nf < 16; nf++)
                tmax = fmaxf(tmax, fmaxf(acc[nf][h2 * 2], acc[nf][h2 * 2 + 1]));
            float nm = fmaxf(mst[h2], tmax);
            float f = __expf(mst[h2] - nm);
            Tc[h2] = f * (Tc[h2] + Zc[h2] * (mst[h2] - nm));
            Zc[h2] *= f;
            float zs = 0.f, ts = 0.f;
#pragma unroll
            for (int nf = 0; nf < 16; nf++) {
                float v0 = acc[nf][h2 * 2] - nm;
                float v1 = acc[nf][h2 * 2 + 1] - nm;
                float e0 = __expf(v0), e1 = __expf(v1);
                zs += e0 + e1;
                ts += e0 * v0 + e1 * v1;
            }
            Zc[h2] += zs;
            Tc[h2] += ts;
            mst[h2] = nm;
        }
    }

    // merge across the 4 lanes sharing each row (lane%4 = 0..3)
#pragma unroll
    for (int h2 = 0; h2 < 2; h2++) {
#pragma unroll
        for (int off = 1; off < 4; off <<= 1) {
            float mo = __shfl_xor_sync(0xffffffffu, mst[h2], off, 4);
            float zo = __shfl_xor_sync(0xffffffffu, Zc[h2],  off, 4);
            float to = __shfl_xor_sync(0xffffffffu, Tc[h2],  off, 4);
            float nm = fmaxf(mst[h2], mo);
            float f1 = __expf(mst[h2] - nm), f2 = __expf(mo - nm);
            Tc[h2] = f1 * (Tc[h2] + Zc[h2] * (mst[h2] - nm)) + f2 * (to + zo * (mo - nm));
            Zc[h2] = Zc[h2] * f1 + zo * f2;
            mst[h2] = nm;
        }
        if ((lane & 3) == 0) {
            int q = q0 + wrow0 + (lane >> 2) + h2 * 8;
            g_kl[(size_t)bh * TT + q] = Tc[h2] / Zc[h2] - logf(Zc[h2]);
        }
    }
}

// ---------------------------------------------------------------------------
// Top-3 per (b,h) by KL (jax tie semantics: lower index wins)
// ---------------------------------------------------------------------------
__global__ void top3_kernel() {
    const int bh = blockIdx.x;
    __shared__ float sv[256];
    __shared__ int   si[256];
    __shared__ int   chosen[UU];
    const float* kl = g_kl + (size_t)bh * TT;
    for (int p = 0; p < UU; p++) {
        float bv = -1e38f; int bi = TT;
        for (int q = threadIdx.x; q < TT; q += 256) {
            bool skip = false;
            for (int c = 0; c < p; c++) if (chosen[c] == q) skip = true;
            if (skip) continue;
            float v = kl[q];
            if (v > bv || (v == bv && q < bi)) { bv = v; bi = q; }
        }
        sv[threadIdx.x] = bv; si[threadIdx.x] = bi;
        __syncthreads();
        for (int s = 128; s > 0; s >>= 1) {
            if (threadIdx.x < s) {
                float ov = sv[threadIdx.x + s]; int oi = si[threadIdx.x + s];
                if (ov > sv[threadIdx.x] ||
                    (ov == sv[threadIdx.x] && oi < si[threadIdx.x])) {
                    sv[threadIdx.x] = ov; si[threadIdx.x] = oi;
                }
            }
            __syncthreads();
        }
        if (threadIdx.x == 0) { chosen[p] = si[0]; g_top[bh * UU + p] = si[0]; }
        __syncthreads();
    }
}

// ---------------------------------------------------------------------------
// Reduced attention, split-K: grid (48 slots, 8 parts), 256 keys per part.
// ---------------------------------------------------------------------------
__global__ __launch_bounds__(256) void redattn_part_kernel() {
    const int slot = blockIdx.x;
    const int part = blockIdx.y;
    const int bh = slot / UU;
    const int t = g_top[slot];
    __shared__ float qrow[64];
    __shared__ float sarr[256];
    __shared__ float red[256];
    const int tid = threadIdx.x;

    if (tid < 64) qrow[tid] = g_Q[((size_t)bh * TT + t) * DD + tid];
    __syncthreads();

    const int k = part * 256 + tid;
    {
        const float* kr = g_K + ((size_t)bh * TT + k) * DD;
        float s = 0.f;
#pragma unroll
        for (int d = 0; d < 64; d++) s = fmaf(qrow[d], kr[d], s);
        s *= 0.125f;
        if (!(s == s)) s = -10000.0f;
        s = fminf(fmaxf(s, -10000.0f), 10000.0f);
        sarr[tid] = s;
        red[tid] = s;
    }
    __syncthreads();
    for (int s = 128; s > 0; s >>= 1) {
        if (tid < s) red[tid] = fmaxf(red[tid], red[tid + s]);
        __syncthreads();
    }
    const float mx = red[0];
    __syncthreads();

    float e = expf(sarr[tid] - mx);
    sarr[tid] = e;
    red[tid] = e;
    __syncthreads();
    for (int s = 128; s > 0; s >>= 1) {
        if (tid < s) red[tid] += red[tid + s];
        __syncthreads();
    }
    const float Zp = red[0];
    __syncthreads();

    const int d = tid % 64, gi = tid / 64;
    float acc = 0.f;
    for (int kk = gi; kk < 256; kk += 4)
        acc = fmaf(sarr[kk], g_V[((size_t)bh * TT + part * 256 + kk) * DD + d], acc);
    red[tid] = acc; __syncthreads();

    float* pp = g_part + (size_t)(slot * 8 + part) * 68;
    if (tid == 0) { pp[0] = mx; pp[1] = Zp; }
    if (tid < 64)
        pp[2 + tid] = red[tid] + red[tid + 64] + red[tid + 128] + red[tid + 192];
}

__global__ void redattn_combine_kernel() {
    const int slot = blockIdx.x;
    const int d = threadIdx.x;   // 64 threads
    float mstar = -1e30f;
#pragma unroll
    for (int p = 0; p < 8; p++)
        mstar = fmaxf(mstar, g_part[(size_t)(slot * 8 + p) * 68]);
    float Z = 0.f, acc = 0.f;
#pragma unroll
    for (int p = 0; p < 8; p++) {
        const float* pp = g_part + (size_t)(slot * 8 + p) * 68;
        float f = expf(pp[0] - mstar);
        Z += pp[1] * f;
        acc += pp[2 + d] * f;
    }
    g_or[(size_t)slot * DD + d] = acc / Z;
}

// ---------------------------------------------------------------------------
// Output: init to bias, then sparse-project the 48 nonzero rows with Wo
// ---------------------------------------------------------------------------
__global__ void init_out_kernel(float* __restrict__ out, const float* __restrict__ bo) {
    int idx = blockIdx.x * 256 + threadIdx.x;
    if (idx < BB * TT * DMM) out[idx] = bo[idx % DMM];
}

__global__ void scatter_kernel(const float* __restrict__ Wo, float* __restrict__ out) {
    const int slot = blockIdx.x;
    const int bh = slot / UU;
    const int b = bh / HH, h = bh % HH;
    const int t = g_top[slot];
    __shared__ float orow[64];
    if (threadIdx.x < 64) orow[threadIdx.x] = g_or[(size_t)slot * DD + threadIdx.x];
    __syncthreads();
    for (int n = threadIdx.x; n < DMM; n += 256) {
        const float* wr = Wo + (size_t)n * DMM + h * DD;
        float acc = 0.f;
#pragma unroll
        for (int d = 0; d < 64; d++) acc = fmaf(orow[d], wr[d], acc);
        atomicAdd(&out[((size_t)b * TT + t) * DMM + n], acc);
    }
}

// ---------------------------------------------------------------------------
extern "C" void kernel_launch(void* const* d_in, const int* in_sizes, int n_in,
                              void* d_out, int out_size) {
    const float* query = (const float*)d_in[0];
    const float* key   = (const float*)d_in[1];
    const float* value = (const float*)d_in[2];
    const float* Wq = (const float*)d_in[3];
    const float* bq = (const float*)d_in[4];
    const float* Wk = (const float*)d_in[5];
    const float* bk = (const float*)d_in[6];
    const float* Wv = (const float*)d_in[7];
    const float* bv = (const float*)d_in[8];
    const float* Wo = (const float*)d_in[9];
    const float* bo = (const float*)d_in[10];
    float* out = (float*)d_out;

    float *Qp, *Kp, *Vp;
    cudaGetSymbolAddress((void**)&Qp, g_Q);
    cudaGetSymbolAddress((void**)&Kp, g_K);
    cudaGetSymbolAddress((void**)&Vp, g_V);

    const int gemm_smem = 65536 + 1024;
    cudaFuncSetAttribute(proj_mma_kernel, cudaFuncAttributeMaxDynamicSharedMemorySize, gemm_smem);
    cudaFuncSetAttribute(kl_mma_kernel,   cudaFuncAttributeMaxDynamicSharedMemorySize, gemm_smem);

    convx_kernel<<<dim3(1024, 3), 256>>>(query, key, value);
    convw_kernel<<<dim3(128, 3), 256>>>(Wq, Wk, Wv);

    proj_mma_kernel<<<dim3(4, 32, 3), 256, gemm_smem>>>(bq, bk, bv, Qp, Kp, Vp);

    kl_mma_kernel<<<dim3(16, 16), 256, gemm_smem>>>();

    top3_kernel<<<BH, 256>>>();
    redattn_part_kernel<<<dim3(BH * UU, 8), 256>>>();
    redattn_combine_kernel<<<BH * UU, 64>>>();

    init_out_kernel<<<(BB * TT * DMM + 255) / 256, 256>>>(out, bo);
    scatter_kernel<<<BH * UU, 256>>>(Wo, out);
}

// round 8
// speedup vs baseline: 2.8541x; 1.6794x over previous
#include <cuda_runtime.h>
#include <cuda_bf16.h>
#include <math.h>
#include <stdint.h>

#define BB 2
#define TT 2048
#define DMM 512
#define HH 8
#define DD 64
#define UU 3
#define BH (BB*HH)

typedef unsigned long long u64;

// fp32 scratch
__device__ float g_Q[BH*TT*DD];    // [b,h,t,d]
__device__ float g_K[BH*TT*DD];
__device__ float g_V[BH*TT*DD];
__device__ float g_kl[BH*TT];
__device__ int   g_top[BH*UU];
__device__ float g_or[BH*UU*DD];
__device__ float g_part[BH*UU*8*68];

// bf16 hi/lo packed (bf16x2 per uint), row-major
__device__ unsigned g_Xh[3*4096*256];   // [z][m][k/2]
__device__ unsigned g_Xl[3*4096*256];
__device__ unsigned g_Wh[3*512*256];    // [z][n][k/2]
__device__ unsigned g_Wl[3*512*256];
__device__ unsigned g_Qh[BH*TT*32];     // [bh][t][d/2]  (scaled by log2e/8)
__device__ unsigned g_Ql[BH*TT*32];
__device__ unsigned g_Kh[BH*TT*32];
__device__ unsigned g_Kl[BH*TT*32];

// ---------------------------------------------------------------------------
__device__ __forceinline__ uint32_t smem_u32(const void* p) {
    uint32_t a;
    asm("{ .reg .u64 t; cvta.to.shared.u64 t, %1; cvt.u32.u64 %0, t; }" : "=r"(a) : "l"(p));
    return a;
}
__device__ __forceinline__ void ldsm4(uint32_t addr, uint32_t& r0, uint32_t& r1,
                                      uint32_t& r2, uint32_t& r3) {
    asm volatile("ldmatrix.sync.aligned.m8n8.x4.shared.b16 {%0,%1,%2,%3}, [%4];"
                 : "=r"(r0), "=r"(r1), "=r"(r2), "=r"(r3) : "r"(addr));
}
__device__ __forceinline__ void mma_bf16(float& c0, float& c1, float& c2, float& c3,
                                         uint32_t a0, uint32_t a1, uint32_t a2, uint32_t a3,
                                         uint32_t b0, uint32_t b1) {
    asm("mma.sync.aligned.m16n8k16.row.col.f32.bf16.bf16.f32 "
        "{%0,%1,%2,%3}, {%4,%5,%6,%7}, {%8,%9}, {%0,%1,%2,%3};"
        : "+f"(c0), "+f"(c1), "+f"(c2), "+f"(c3)
        : "r"(a0), "r"(a1), "r"(a2), "r"(a3), "r"(b0), "r"(b1));
}
__device__ __forceinline__ float ex2f(float x) {
    float r;
    asm("ex2.approx.ftz.f32 %0, %1;" : "=f"(r) : "f"(x));
    return r;
}
#define CP_ASYNC16(dst, src) \
    asm volatile("cp.async.cg.shared.global [%0], [%1], 16;" :: "r"(dst), "l"(src))
#define CP_COMMIT() asm volatile("cp.async.commit_group;" ::: "memory")
#define CP_WAIT1()  asm volatile("cp.async.wait_group 1;" ::: "memory")
#define CP_WAIT0()  asm volatile("cp.async.wait_group 0;" ::: "memory")

// ---------------------------------------------------------------------------
// fp32 -> bf16 hi/lo split
// ---------------------------------------------------------------------------
__device__ __forceinline__ void split8(const float* src, uint4& hi, uint4& lo) {
    float4 a = *(const float4*)src;
    float4 b = *(const float4*)(src + 4);
    float v[8] = {a.x, a.y, a.z, a.w, b.x, b.y, b.z, b.w};
    unsigned h16[8], l16[8];
#pragma unroll
    for (int i = 0; i < 8; i++) {
        __nv_bfloat16 h = __float2bfloat16_rn(v[i]);
        float r = v[i] - __bfloat162float(h);
        __nv_bfloat16 l = __float2bfloat16_rn(r);
        h16[i] = __bfloat16_as_ushort(h);
        l16[i] = __bfloat16_as_ushort(l);
    }
    hi = make_uint4(h16[0] | (h16[1] << 16), h16[2] | (h16[3] << 16),
                    h16[4] | (h16[5] << 16), h16[6] | (h16[7] << 16));
    lo = make_uint4(l16[0] | (l16[1] << 16), l16[2] | (l16[3] << 16),
                    l16[4] | (l16[5] << 16), l16[6] | (l16[7] << 16));
}

__global__ __launch_bounds__(256) void convx_kernel(
    const float* __restrict__ X0, const float* __restrict__ X1, const float* __restrict__ X2)
{
    const int z = blockIdx.y;
    const float* X = (z == 0) ? X0 : (z == 1) ? X1 : X2;
    int idx = blockIdx.x * 256 + threadIdx.x;
    uint4 hi, lo;
    split8(X + (size_t)idx * 8, hi, lo);
    size_t di = (size_t)z * 4096 * 64 + idx;
    ((uint4*)g_Xh)[di] = hi;
    ((uint4*)g_Xl)[di] = lo;
}

__global__ __launch_bounds__(256) void convw_kernel(
    const float* __restrict__ W0, const float* __restrict__ W1, const float* __restrict__ W2)
{
    const int z = blockIdx.y;
    const float* W = (z == 0) ? W0 : (z == 1) ? W1 : W2;
    int idx = blockIdx.x * 256 + threadIdx.x;
    uint4 hi, lo;
    split8(W + (size_t)idx * 8, hi, lo);
    size_t di = (size_t)z * 512 * 64 + idx;
    ((uint4*)g_Wh)[di] = hi;
    ((uint4*)g_Wl)[di] = lo;
}

// ---------------------------------------------------------------------------
// Projection via mma.sync bf16 3-term split, cp.async double-buffered.
// grid (nt=4, mt=32, z=3), 256 thr. Block tile 128x128.
// smem: 2 stages x 64KB (Xh,Xl,Wh,Wl 16KB each)
// ---------------------------------------------------------------------------
__global__ __launch_bounds__(256) void proj_mma_kernel(
    const float* __restrict__ B0, const float* __restrict__ B1, const float* __restrict__ B2,
    float* __restrict__ P0, float* __restrict__ P1, float* __restrict__ P2)
{
    extern __shared__ char dsm[];
    char* sbase = (char*)(((uintptr_t)dsm + 1023u) & ~(uintptr_t)1023u);
    const uint32_t sb = smem_u32(sbase);

    const int z = blockIdx.z;
    const float* Bv = (z == 0) ? B0 : (z == 1) ? B1 : B2;
    float*       P = (z == 0) ? P0 : (z == 1) ? P1 : P2;
    const int nt = blockIdx.x, mt = blockIdx.y;
    const int tid = threadIdx.x;
    const int wid = tid >> 5, lane = tid & 31;
    const int r = lane & 7, g = lane >> 3;
    const int wrow0 = wid * 16;
    const int m0 = mt * 128, n0 = nt * 128;

    float acc[16][4];
#pragma unroll
    for (int i = 0; i < 16; i++)
#pragma unroll
        for (int j = 0; j < 4; j++) acc[i][j] = 0.f;

    const int rowA = wrow0 + r + (g & 1) * 8;
    const int gbA = g >> 1;
    const int gbB = g & 1;
    const int rowBoff = r + ((g >> 1) & 1) * 8;

    auto prefetch = [&](int kc) {
        uint32_t stg = sb + (kc & 1) * 65536;
#pragma unroll
        for (int j = 0; j < 4; j++) {
            int i = tid + j * 256;
            int row = i >> 3, c = i & 7;
            uint32_t boff = row * 128 + c * 16;
            uint32_t swb = boff ^ ((boff >> 3) & 0x70);
            size_t sx = (size_t)(z * 4096 + m0 + row) * 64 + kc * 8 + c;
            size_t swi = (size_t)(z * 512 + n0 + row) * 64 + kc * 8 + c;
            CP_ASYNC16(stg + swb,         (const uint4*)g_Xh + sx);
            CP_ASYNC16(stg + 16384 + swb, (const uint4*)g_Xl + sx);
            CP_ASYNC16(stg + 32768 + swb, (const uint4*)g_Wh + swi);
            CP_ASYNC16(stg + 49152 + swb, (const uint4*)g_Wl + swi);
        }
    };

    prefetch(0); CP_COMMIT();

    for (int kc = 0; kc < 8; kc++) {
        if (kc < 7) { prefetch(kc + 1); CP_COMMIT(); CP_WAIT1(); }
        else CP_WAIT0();
        __syncthreads();
        const uint32_t stg = sb + (kc & 1) * 65536;
        const uint32_t abase = stg + rowA * 128;

#pragma unroll
        for (int ks = 0; ks < 4; ks++) {
            uint32_t aoffs = ((uint32_t)((ks * 2 + gbA) * 16)) ^ (uint32_t)(r * 16);
            uint32_t ah0, ah1, ah2, ah3, al0, al1, al2, al3;
            ldsm4(abase + aoffs, ah0, ah1, ah2, ah3);
            ldsm4(abase + 16384 + aoffs, al0, al1, al2, al3);
            uint32_t boffs = ((uint32_t)((ks * 2 + gbB) * 16)) ^ (uint32_t)(r * 16);
#pragma unroll
            for (int np = 0; np < 8; np++) {
                uint32_t bbase = stg + 32768 + (np * 16 + rowBoff) * 128 + boffs;
                uint32_t bh0, bh1, bh2, bh3, bl0, bl1, bl2, bl3;
                ldsm4(bbase, bh0, bh1, bh2, bh3);
                ldsm4(bbase + 16384, bl0, bl1, bl2, bl3);
                int f0 = np * 2, f1 = np * 2 + 1;
                mma_bf16(acc[f0][0], acc[f0][1], acc[f0][2], acc[f0][3],
                         ah0, ah1, ah2, ah3, bh0, bh1);
                mma_bf16(acc[f1][0], acc[f1][1], acc[f1][2], acc[f1][3],
                         ah0, ah1, ah2, ah3, bh2, bh3);
                mma_bf16(acc[f0][0], acc[f0][1], acc[f0][2], acc[f0][3],
                         ah0, ah1, ah2, ah3, bl0, bl1);
                mma_bf16(acc[f1][0], acc[f1][1], acc[f1][2], acc[f1][3],
                         ah0, ah1, ah2, ah3, bl2, bl3);
                mma_bf16(acc[f0][0], acc[f0][1], acc[f0][2], acc[f0][3],
                         al0, al1, al2, al3, bh0, bh1);
                mma_bf16(acc[f1][0], acc[f1][1], acc[f1][2], acc[f1][3],
                         al0, al1, al2, al3, bh2, bh3);
            }
        }
        __syncthreads();
    }

    // epilogue; Q gets log2-domain scale folded in
    const float QSCALE = 0.18033688011112042f;   // 0.125 * log2(e)
    const int mrow0 = m0 + wrow0 + (lane >> 2);
#pragma unroll
    for (int half = 0; half < 2; half++) {
        int m = mrow0 + half * 8;
        int b = m >> 11, t = m & 2047;
#pragma unroll
        for (int nf = 0; nf < 16; nf++) {
            int n = n0 + nf * 8 + 2 * (lane & 3);
            int h = n >> 6, d = n & 63;
            float2 bias = *(const float2*)(Bv + n);
            float v0 = acc[nf][half * 2] + bias.x;
            float v1 = acc[nf][half * 2 + 1] + bias.y;
            size_t po = (((size_t)(b * HH + h)) * TT + t) * DD + d;
            *(float2*)&P[po] = make_float2(v0, v1);
            if (z < 2) {
                float s0 = v0, s1 = v1;
                if (z == 0) { s0 *= QSCALE; s1 *= QSCALE; }
                __nv_bfloat16 h0 = __float2bfloat16_rn(s0);
                __nv_bfloat16 h1 = __float2bfloat16_rn(s1);
                float l0 = s0 - __bfloat162float(h0);
                float l1 = s1 - __bfloat162float(h1);
                unsigned hp = (unsigned)__bfloat16_as_ushort(h0) |
                              ((unsigned)__bfloat16_as_ushort(h1) << 16);
                unsigned lp = (unsigned)__bfloat16_as_ushort(__float2bfloat16_rn(l0)) |
                              ((unsigned)__bfloat16_as_ushort(__float2bfloat16_rn(l1)) << 16);
                size_t qo = (((size_t)(b * HH + h)) * TT + t) * 32 + (d >> 1);
                if (z == 0) { g_Qh[qo] = hp; g_Ql[qo] = lp; }
                else        { g_Kh[qo] = hp; g_Kl[qo] = lp; }
            }
        }
    }
}

// ---------------------------------------------------------------------------
// KL statistic: base-2 online softmax, cp.async double-buffered K tiles.
// smem: Q (32KB) + 2 K stages (32KB each) = 96KB.
// ---------------------------------------------------------------------------
__global__ __launch_bounds__(256) void kl_mma_kernel() {
    extern __shared__ char dsm[];
    char* sbase = (char*)(((uintptr_t)dsm + 1023u) & ~(uintptr_t)1023u);
    const uint32_t sb = smem_u32(sbase);

    const int tid = threadIdx.x;
    const int wid = tid >> 5, lane = tid & 31;
    const int r = lane & 7, g = lane >> 3;
    const int wrow0 = wid * 16;
    const int bh = blockIdx.y;
    const int q0 = blockIdx.x * 128;

    auto prefetchK = [&](int kt) {
        uint32_t stg = sb + 32768 + (kt & 1) * 32768;
#pragma unroll
        for (int j = 0; j < 4; j++) {
            int i = tid + j * 256;
            int row = i >> 3, c = i & 7;
            uint32_t boff = row * 128 + c * 16;
            uint32_t swb = boff ^ ((boff >> 3) & 0x70);
            size_t sidx = (size_t)(bh * TT + kt * 128 + row) * 8 + c;
            CP_ASYNC16(stg + swb,         (const uint4*)g_Kh + sidx);
            CP_ASYNC16(stg + 16384 + swb, (const uint4*)g_Kl + sidx);
        }
    };

    prefetchK(0); CP_COMMIT();

    // fill Q tiles (plain stores)
#pragma unroll
    for (int j = 0; j < 4; j++) {
        int i = tid + j * 256;
        int row = i >> 3, c = i & 7;
        uint32_t boff = row * 128 + c * 16;
        uint32_t swb = boff ^ ((boff >> 3) & 0x70);
        size_t sidx = (size_t)(bh * TT + q0 + row) * 8 + c;
        *(uint4*)(sbase + swb)         = ((const uint4*)g_Qh)[sidx];
        *(uint4*)(sbase + 16384 + swb) = ((const uint4*)g_Ql)[sidx];
    }
    __syncthreads();

    // hoist Q fragments for all 4 k-steps
    uint32_t Ah[4][4], Al[4][4];
    {
        const int rowA = wrow0 + r + (g & 1) * 8;
        const uint32_t abase = sb + rowA * 128;
        const int gbA = g >> 1;
#pragma unroll
        for (int ks = 0; ks < 4; ks++) {
            uint32_t aoffs = ((uint32_t)((ks * 2 + gbA) * 16)) ^ (uint32_t)(r * 16);
            ldsm4(abase + aoffs, Ah[ks][0], Ah[ks][1], Ah[ks][2], Ah[ks][3]);
            ldsm4(abase + 16384 + aoffs, Al[ks][0], Al[ks][1], Al[ks][2], Al[ks][3]);
        }
    }

    float mst[2] = {-1e30f, -1e30f}, Zc[2] = {0.f, 0.f}, Tc[2] = {0.f, 0.f};
    const int gbB = g & 1;
    const int rowBoff = r + ((g >> 1) & 1) * 8;

    for (int kt = 0; kt < TT / 128; kt++) {
        if (kt < TT / 128 - 1) { prefetchK(kt + 1); CP_COMMIT(); CP_WAIT1(); }
        else CP_WAIT0();
        __syncthreads();
        const uint32_t stg = sb + 32768 + (kt & 1) * 32768;

        float acc[16][4];
#pragma unroll
        for (int i = 0; i < 16; i++)
#pragma unroll
            for (int j = 0; j < 4; j++) acc[i][j] = 0.f;

#pragma unroll
        for (int ks = 0; ks < 4; ks++) {
            uint32_t boffs = ((uint32_t)((ks * 2 + gbB) * 16)) ^ (uint32_t)(r * 16);
#pragma unroll
            for (int np = 0; np < 8; np++) {
                uint32_t bbase = stg + (np * 16 + rowBoff) * 128 + boffs;
                uint32_t bh0, bh1, bh2, bh3, bl0, bl1, bl2, bl3;
                ldsm4(bbase, bh0, bh1, bh2, bh3);
                ldsm4(bbase + 16384, bl0, bl1, bl2, bl3);
                int f0 = np * 2, f1 = np * 2 + 1;
                mma_bf16(acc[f0][0], acc[f0][1], acc[f0][2], acc[f0][3],
                         Ah[ks][0], Ah[ks][1], Ah[ks][2], Ah[ks][3], bh0, bh1);
                mma_bf16(acc[f1][0], acc[f1][1], acc[f1][2], acc[f1][3],
                         Ah[ks][0], Ah[ks][1], Ah[ks][2], Ah[ks][3], bh2, bh3);
                mma_bf16(acc[f0][0], acc[f0][1], acc[f0][2], acc[f0][3],
                         Ah[ks][0], Ah[ks][1], Ah[ks][2], Ah[ks][3], bl0, bl1);
                mma_bf16(acc[f1][0], acc[f1][1], acc[f1][2], acc[f1][3],
                         Ah[ks][0], Ah[ks][1], Ah[ks][2], Ah[ks][3], bl2, bl3);
                mma_bf16(acc[f0][0], acc[f0][1], acc[f0][2], acc[f0][3],
                         Al[ks][0], Al[ks][1], Al[ks][2], Al[ks][3], bh0, bh1);
                mma_bf16(acc[f1][0], acc[f1][1], acc[f1][2], acc[f1][3],
                         Al[ks][0], Al[ks][1], Al[ks][2], Al[ks][3], bh2, bh3);
            }
        }

        // base-2 online softmax/KL update; scores already in log2 domain
#pragma unroll
        for (int h2 = 0; h2 < 2; h2++) {
            float tmax = -1e30f;
#pragma unroll
            for (int nf = 0; nf < 16; nf++)
                tmax = fmaxf(tmax, fmaxf(acc[nf][h2 * 2], acc[nf][h2 * 2 + 1]));
            float nm = fmaxf(mst[h2], tmax);
            float f = ex2f(mst[h2] - nm);
            float zs = 0.f, ts = 0.f;
#pragma unroll
            for (int nf = 0; nf < 16; nf++) {
                float u0 = acc[nf][h2 * 2];
                float u1 = acc[nf][h2 * 2 + 1];
                float e0 = ex2f(u0 - nm);
                float e1 = ex2f(u1 - nm);
                zs += e0 + e1;
                ts = fmaf(e0, u0, ts);
                ts = fmaf(e1, u1, ts);
            }
            Zc[h2] = Zc[h2] * f + zs;
            Tc[h2] = Tc[h2] * f + ts;
            mst[h2] = nm;
        }
        __syncthreads();
    }

    // merge across the 4 lanes sharing each row
#pragma unroll
    for (int h2 = 0; h2 < 2; h2++) {
#pragma unroll
        for (int off = 1; off < 4; off <<= 1) {
            float mo = __shfl_xor_sync(0xffffffffu, mst[h2], off, 4);
            float zo = __shfl_xor_sync(0xffffffffu, Zc[h2],  off, 4);
            float to = __shfl_xor_sync(0xffffffffu, Tc[h2],  off, 4);
            float nm = fmaxf(mst[h2], mo);
            float f1 = ex2f(mst[h2] - nm), f2 = ex2f(mo - nm);
            Zc[h2] = Zc[h2] * f1 + zo * f2;
            Tc[h2] = Tc[h2] * f1 + to * f2;
            mst[h2] = nm;
        }
        if ((lane & 3) == 0) {
            int q = q0 + wrow0 + (lane >> 2) + h2 * 8;
            float rkl = 0.6931471805599453f *
                        (Tc[h2] / Zc[h2] - mst[h2] - log2f(Zc[h2]));
            g_kl[(size_t)bh * TT + q] = rkl;
        }
    }
}

// ---------------------------------------------------------------------------
// Top-3 per (b,h) by KL (jax tie semantics: lower index wins)
// ---------------------------------------------------------------------------
__global__ void top3_kernel() {
    const int bh = blockIdx.x;
    __shared__ float sv[256];
    __shared__ int   si[256];
    __shared__ int   chosen[UU];
    const float* kl = g_kl + (size_t)bh * TT;
    for (int p = 0; p < UU; p++) {
        float bv = -1e38f; int bi = TT;
        for (int q = threadIdx.x; q < TT; q += 256) {
            bool skip = false;
            for (int c = 0; c < p; c++) if (chosen[c] == q) skip = true;
            if (skip) continue;
            float v = kl[q];
            if (v > bv || (v == bv && q < bi)) { bv = v; bi = q; }
        }
        sv[threadIdx.x] = bv; si[threadIdx.x] = bi;
        __syncthreads();
        for (int s = 128; s > 0; s >>= 1) {
            if (threadIdx.x < s) {
                float ov = sv[threadIdx.x + s]; int oi = si[threadIdx.x + s];
                if (ov > sv[threadIdx.x] ||
                    (ov == sv[threadIdx.x] && oi < si[threadIdx.x])) {
                    sv[threadIdx.x] = ov; si[threadIdx.x] = oi;
                }
            }
            __syncthreads();
        }
        if (threadIdx.x == 0) { chosen[p] = si[0]; g_top[bh * UU + p] = si[0]; }
        __syncthreads();
    }
}

// ---------------------------------------------------------------------------
// Reduced attention, split-K: grid (48 slots, 8 parts), 256 keys per part.
// ---------------------------------------------------------------------------
__global__ __launch_bounds__(256) void redattn_part_kernel() {
    const int slot = blockIdx.x;
    const int part = blockIdx.y;
    const int bh = slot / UU;
    const int t = g_top[slot];
    __shared__ float qrow[64];
    __shared__ float sarr[256];
    __shared__ float red[256];
    const int tid = threadIdx.x;

    if (tid < 64) qrow[tid] = g_Q[((size_t)bh * TT + t) * DD + tid];
    __syncthreads();

    const int k = part * 256 + tid;
    {
        const float* kr = g_K + ((size_t)bh * TT + k) * DD;
        float s = 0.f;
#pragma unroll
        for (int d = 0; d < 64; d++) s = fmaf(qrow[d], kr[d], s);
        s *= 0.125f;
        if (!(s == s)) s = -10000.0f;
        s = fminf(fmaxf(s, -10000.0f), 10000.0f);
        sarr[tid] = s;
        red[tid] = s;
    }
    __syncthreads();
    for (int s = 128; s > 0; s >>= 1) {
        if (tid < s) red[tid] = fmaxf(red[tid], red[tid + s]);
        __syncthreads();
    }
    const float mx = red[0];
    __syncthreads();

    float e = expf(sarr[tid] - mx);
    sarr[tid] = e;
    red[tid] = e;
    __syncthreads();
    for (int s = 128; s > 0; s >>= 1) {
        if (tid < s) red[tid] += red[tid + s];
        __syncthreads();
    }
    const float Zp = red[0];
    __syncthreads();

    const int d = tid % 64, gi = tid / 64;
    float acc = 0.f;
    for (int kk = gi; kk < 256; kk += 4)
        acc = fmaf(sarr[kk], g_V[((size_t)bh * TT + part * 256 + kk) * DD + d], acc);
    red[tid] = acc; __syncthreads();

    float* pp = g_part + (size_t)(slot * 8 + part) * 68;
    if (tid == 0) { pp[0] = mx; pp[1] = Zp; }
    if (tid < 64)
        pp[2 + tid] = red[tid] + red[tid + 64] + red[tid + 128] + red[tid + 192];
}

__global__ void redattn_combine_kernel() {
    const int slot = blockIdx.x;
    const int d = threadIdx.x;   // 64 threads
    float mstar = -1e30f;
#pragma unroll
    for (int p = 0; p < 8; p++)
        mstar = fmaxf(mstar, g_part[(size_t)(slot * 8 + p) * 68]);
    float Z = 0.f, acc = 0.f;
#pragma unroll
    for (int p = 0; p < 8; p++) {
        const float* pp = g_part + (size_t)(slot * 8 + p) * 68;
        float f = expf(pp[0] - mstar);
        Z += pp[1] * f;
        acc += pp[2 + d] * f;
    }
    g_or[(size_t)slot * DD + d] = acc / Z;
}

// ---------------------------------------------------------------------------
// Output: init to bias, then sparse-project the 48 nonzero rows with Wo
// ---------------------------------------------------------------------------
__global__ void init_out_kernel(float* __restrict__ out, const float* __restrict__ bo) {
    int idx = blockIdx.x * 256 + threadIdx.x;
    if (idx < BB * TT * DMM) out[idx] = bo[idx % DMM];
}

__global__ void scatter_kernel(const float* __restrict__ Wo, float* __restrict__ out) {
    const int slot = blockIdx.x;
    const int bh = slot / UU;
    const int b = bh / HH, h = bh % HH;
    const int t = g_top[slot];
    __shared__ float orow[64];
    if (threadIdx.x < 64) orow[threadIdx.x] = g_or[(size_t)slot * DD + threadIdx.x];
    __syncthreads();
    for (int n = threadIdx.x; n < DMM; n += 256) {
        const float* wr = Wo + (size_t)n * DMM + h * DD;
        float acc = 0.f;
#pragma unroll
        for (int d = 0; d < 64; d++) acc = fmaf(orow[d], wr[d], acc);
        atomicAdd(&out[((size_t)b * TT + t) * DMM + n], acc);
    }
}

// ---------------------------------------------------------------------------
extern "C" void kernel_launch(void* const* d_in, const int* in_sizes, int n_in,
                              void* d_out, int out_size) {
    const float* query = (const float*)d_in[0];
    const float* key   = (const float*)d_in[1];
    const float* value = (const float*)d_in[2];
    const float* Wq = (const float*)d_in[3];
    const float* bq = (const float*)d_in[4];
    const float* Wk = (const float*)d_in[5];
    const float* bk = (const float*)d_in[6];
    const float* Wv = (const float*)d_in[7];
    const float* bv = (const float*)d_in[8];
    const float* Wo = (const float*)d_in[9];
    const float* bo = (const float*)d_in[10];
    float* out = (float*)d_out;

    float *Qp, *Kp, *Vp;
    cudaGetSymbolAddress((void**)&Qp, g_Q);
    cudaGetSymbolAddress((void**)&Kp, g_K);
    cudaGetSymbolAddress((void**)&Vp, g_V);

    const int proj_smem = 131072 + 1024;
    const int kl_smem   = 98304 + 1024;
    cudaFuncSetAttribute(proj_mma_kernel, cudaFuncAttributeMaxDynamicSharedMemorySize, proj_smem);
    cudaFuncSetAttribute(kl_mma_kernel,   cudaFuncAttributeMaxDynamicSharedMemorySize, kl_smem);

    convx_kernel<<<dim3(1024, 3), 256>>>(query, key, value);
    convw_kernel<<<dim3(128, 3), 256>>>(Wq, Wk, Wv);

    proj_mma_kernel<<<dim3(4, 32, 3), 256, proj_smem>>>(bq, bk, bv, Qp, Kp, Vp);

    kl_mma_kernel<<<dim3(16, 16), 256, kl_smem>>>();

    top3_kernel<<<BH, 256>>>();
    redattn_part_kernel<<<dim3(BH * UU, 8), 256>>>();
    redattn_combine_kernel<<<BH * UU, 64>>>();

    init_out_kernel<<<(BB * TT * DMM + 255) / 256, 256>>>(out, bo);
    scatter_kernel<<<BH * UU, 256>>>(Wo, out);
}

// round 11
// speedup vs baseline: 2.9293x; 1.0263x over previous
#include <cuda_runtime.h>
#include <cuda_bf16.h>
#include <math.h>
#include <stdint.h>

#define BB 2
#define TT 2048
#define DMM 512
#define HH 8
#define DD 64
#define UU 3
#define BH (BB*HH)

typedef unsigned long long u64;

// fp32 scratch
__device__ float g_Q[BH*TT*DD];    // [b,h,t,d]
__device__ float g_K[BH*TT*DD];
__device__ float g_V[BH*TT*DD];
__device__ float g_kl[BH*TT];
__device__ int   g_top[BH*UU];
__device__ float g_or[BH*UU*DD];
__device__ float g_part[BH*UU*8*68];
__device__ float g_kp[2*BH*TT*4];   // kl split-K partials: m, Z, T, pad

// bf16 hi/lo packed (bf16x2 per uint), row-major
__device__ unsigned g_Xh[3*4096*256];   // [z][m][k/2]
__device__ unsigned g_Xl[3*4096*256];
__device__ unsigned g_Wh[3*512*256];    // [z][n][k/2]
__device__ unsigned g_Wl[3*512*256];
__device__ unsigned g_Qh[BH*TT*32];     // [bh][t][d/2]  (scaled by log2e/8)
__device__ unsigned g_Ql[BH*TT*32];
__device__ unsigned g_Kh[BH*TT*32];
__device__ unsigned g_Kl[BH*TT*32];

// ---------------------------------------------------------------------------
__device__ __forceinline__ uint32_t smem_u32(const void* p) {
    uint32_t a;
    asm("{ .reg .u64 t; cvta.to.shared.u64 t, %1; cvt.u32.u64 %0, t; }" : "=r"(a) : "l"(p));
    return a;
}
__device__ __forceinline__ void ldsm4(uint32_t addr, uint32_t& r0, uint32_t& r1,
                                      uint32_t& r2, uint32_t& r3) {
    asm volatile("ldmatrix.sync.aligned.m8n8.x4.shared.b16 {%0,%1,%2,%3}, [%4];"
                 : "=r"(r0), "=r"(r1), "=r"(r2), "=r"(r3) : "r"(addr));
}
__device__ __forceinline__ void mma_bf16(float& c0, float& c1, float& c2, float& c3,
                                         uint32_t a0, uint32_t a1, uint32_t a2, uint32_t a3,
                                         uint32_t b0, uint32_t b1) {
    asm("mma.sync.aligned.m16n8k16.row.col.f32.bf16.bf16.f32 "
        "{%0,%1,%2,%3}, {%4,%5,%6,%7}, {%8,%9}, {%0,%1,%2,%3};"
        : "+f"(c0), "+f"(c1), "+f"(c2), "+f"(c3)
        : "r"(a0), "r"(a1), "r"(a2), "r"(a3), "r"(b0), "r"(b1));
}
__device__ __forceinline__ float ex2f(float x) {
    float r;
    asm("ex2.approx.ftz.f32 %0, %1;" : "=f"(r) : "f"(x));
    return r;
}
#define CP_ASYNC16(dst, src) \
    asm volatile("cp.async.cg.shared.global [%0], [%1], 16;" :: "r"(dst), "l"(src))
#define CP_COMMIT() asm volatile("cp.async.commit_group;" ::: "memory")
#define CP_WAIT1()  asm volatile("cp.async.wait_group 1;" ::: "memory")
#define CP_WAIT0()  asm volatile("cp.async.wait_group 0;" ::: "memory")

// ---------------------------------------------------------------------------
// fp32 -> bf16 hi/lo split
// ---------------------------------------------------------------------------
__device__ __forceinline__ void split8(const float* src, uint4& hi, uint4& lo) {
    float4 a = *(const float4*)src;
    float4 b = *(const float4*)(src + 4);
    float v[8] = {a.x, a.y, a.z, a.w, b.x, b.y, b.z, b.w};
    unsigned h16[8], l16[8];
#pragma unroll
    for (int i = 0; i < 8; i++) {
        __nv_bfloat16 h = __float2bfloat16_rn(v[i]);
        float r = v[i] - __bfloat162float(h);
        __nv_bfloat16 l = __float2bfloat16_rn(r);
        h16[i] = __bfloat16_as_ushort(h);
        l16[i] = __bfloat16_as_ushort(l);
    }
    hi = make_uint4(h16[0] | (h16[1] << 16), h16[2] | (h16[3] << 16),
                    h16[4] | (h16[5] << 16), h16[6] | (h16[7] << 16));
    lo = make_uint4(l16[0] | (l16[1] << 16), l16[2] | (l16[3] << 16),
                    l16[4] | (l16[5] << 16), l16[6] | (l16[7] << 16));
}

__global__ __launch_bounds__(256) void convx_kernel(
    const float* __restrict__ X0, const float* __restrict__ X1, const float* __restrict__ X2)
{
    const int z = blockIdx.y;
    const float* X = (z == 0) ? X0 : (z == 1) ? X1 : X2;
    int idx = blockIdx.x * 256 + threadIdx.x;
    uint4 hi, lo;
    split8(X + (size_t)idx * 8, hi, lo);
    size_t di = (size_t)z * 4096 * 64 + idx;
    ((uint4*)g_Xh)[di] = hi;
    ((uint4*)g_Xl)[di] = lo;
}

__global__ __launch_bounds__(256) void convw_kernel(
    const float* __restrict__ W0, const float* __restrict__ W1, const float* __restrict__ W2)
{
    const int z = blockIdx.y;
    const float* W = (z == 0) ? W0 : (z == 1) ? W1 : W2;
    int idx = blockIdx.x * 256 + threadIdx.x;
    uint4 hi, lo;
    split8(W + (size_t)idx * 8, hi, lo);
    size_t di = (size_t)z * 512 * 64 + idx;
    ((uint4*)g_Wh)[di] = hi;
    ((uint4*)g_Wl)[di] = lo;
}

// ---------------------------------------------------------------------------
// Projection via mma.sync bf16 3-term split, cp.async double-buffered, k32
// stages with SW64 swizzle (64B rows) for 2 CTAs/SM residency.
// grid (nt=4, mt=32, z=3), 256 thr. Block tile 128x128.
// smem: 2 stages x 32KB (Xh,Xl,Wh,Wl 8KB each)
// ---------------------------------------------------------------------------
__global__ __launch_bounds__(256, 2) void proj_mma_kernel(
    const float* __restrict__ B0, const float* __restrict__ B1, const float* __restrict__ B2,
    float* __restrict__ P0, float* __restrict__ P1, float* __restrict__ P2)
{
    extern __shared__ char dsm[];
    char* sbase = (char*)(((uintptr_t)dsm + 1023u) & ~(uintptr_t)1023u);
    const uint32_t sb = smem_u32(sbase);

    const int z = blockIdx.z;
    const float* Bv = (z == 0) ? B0 : (z == 1) ? B1 : B2;
    float*       P = (z == 0) ? P0 : (z == 1) ? P1 : P2;
    const int nt = blockIdx.x, mt = blockIdx.y;
    const int tid = threadIdx.x;
    const int wid = tid >> 5, lane = tid & 31;
    const int r = lane & 7, g = lane >> 3;
    const int wrow0 = wid * 16;
    const int m0 = mt * 128, n0 = nt * 128;

    float acc[16][4];
#pragma unroll
    for (int i = 0; i < 16; i++)
#pragma unroll
        for (int j = 0; j < 4; j++) acc[i][j] = 0.f;

    const int rowA = wrow0 + r + (g & 1) * 8;
    const int gbA = g >> 1;
    const int gbB = g & 1;
    const int rowBoff = r + ((g >> 1) & 1) * 8;

    // SW64 per-thread A-row constants (64B rows)
    const uint32_t rbA = (uint32_t)rowA * 64;
    const uint32_t maskA = (rbA >> 3) & 0x30;

    auto prefetch = [&](int kc) {
        uint32_t stg = sb + (kc & 1) * 32768;
#pragma unroll
        for (int j = 0; j < 2; j++) {
            int i = tid + j * 256;          // 0..511
            int row = i >> 2, c = i & 3;
            uint32_t boff = row * 64 + c * 16;
            uint32_t swb = boff ^ ((boff >> 3) & 0x30);
            size_t sx = (size_t)(z * 4096 + m0 + row) * 64 + kc * 4 + c;
            size_t swi = (size_t)(z * 512 + n0 + row) * 64 + kc * 4 + c;
            CP_ASYNC16(stg + swb,         (const uint4*)g_Xh + sx);
            CP_ASYNC16(stg + 8192 + swb,  (const uint4*)g_Xl + sx);
            CP_ASYNC16(stg + 16384 + swb, (const uint4*)g_Wh + swi);
            CP_ASYNC16(stg + 24576 + swb, (const uint4*)g_Wl + swi);
        }
    };

    prefetch(0); CP_COMMIT();

    for (int kc = 0; kc < 16; kc++) {
        if (kc < 15) { prefetch(kc + 1); CP_COMMIT(); CP_WAIT1(); }
        else CP_WAIT0();
        __syncthreads();
        const uint32_t stg = sb + (kc & 1) * 32768;
        const uint32_t abase = stg + rbA;

#pragma unroll
        for (int ks = 0; ks < 2; ks++) {
            uint32_t aoffs = ((uint32_t)((ks * 2 + gbA) * 16)) ^ maskA;
            uint32_t ah0, ah1, ah2, ah3, al0, al1, al2, al3;
            ldsm4(abase + aoffs, ah0, ah1, ah2, ah3);
            ldsm4(abase + 8192 + aoffs, al0, al1, al2, al3);
            uint32_t chunkB = (uint32_t)((ks * 2 + gbB) * 16);
#pragma unroll
            for (int np = 0; np < 8; np++) {
                uint32_t rbB = (uint32_t)(np * 16 + rowBoff) * 64;
                uint32_t boffs = chunkB ^ ((rbB >> 3) & 0x30);
                uint32_t bbase = stg + 16384 + rbB + boffs;
                uint32_t bh0, bh1, bh2, bh3, bl0, bl1, bl2, bl3;
                ldsm4(bbase, bh0, bh1, bh2, bh3);
                ldsm4(bbase + 8192, bl0, bl1, bl2, bl3);
                int f0 = np * 2, f1 = np * 2 + 1;
                mma_bf16(acc[f0][0], acc[f0][1], acc[f0][2], acc[f0][3],
                         ah0, ah1, ah2, ah3, bh0, bh1);
                mma_bf16(acc[f1][0], acc[f1][1], acc[f1][2], acc[f1][3],
                         ah0, ah1, ah2, ah3, bh2, bh3);
                mma_bf16(acc[f0][0], acc[f0][1], acc[f0][2], acc[f0][3],
                         ah0, ah1, ah2, ah3, bl0, bl1);
                mma_bf16(acc[f1][0], acc[f1][1], acc[f1][2], acc[f1][3],
                         ah0, ah1, ah2, ah3, bl2, bl3);
                mma_bf16(acc[f0][0], acc[f0][1], acc[f0][2], acc[f0][3],
                         al0, al1, al2, al3, bh0, bh1);
                mma_bf16(acc[f1][0], acc[f1][1], acc[f1][2], acc[f1][3],
                         al0, al1, al2, al3, bh2, bh3);
            }
        }
        __syncthreads();
    }

    // epilogue; Q gets log2-domain scale folded in
    const float QSCALE = 0.18033688011112042f;   // 0.125 * log2(e)
    const int mrow0 = m0 + wrow0 + (lane >> 2);
#pragma unroll
    for (int half = 0; half < 2; half++) {
        int m = mrow0 + half * 8;
        int b = m >> 11, t = m & 2047;
#pragma unroll
        for (int nf = 0; nf < 16; nf++) {
            int n = n0 + nf * 8 + 2 * (lane & 3);
            int h = n >> 6, d = n & 63;
            float2 bias = *(const float2*)(Bv + n);
            float v0 = acc[nf][half * 2] + bias.x;
            float v1 = acc[nf][half * 2 + 1] + bias.y;
            size_t po = (((size_t)(b * HH + h)) * TT + t) * DD + d;
            *(float2*)&P[po] = make_float2(v0, v1);
            if (z < 2) {
                float s0 = v0, s1 = v1;
                if (z == 0) { s0 *= QSCALE; s1 *= QSCALE; }
                __nv_bfloat16 h0 = __float2bfloat16_rn(s0);
                __nv_bfloat16 h1 = __float2bfloat16_rn(s1);
                float l0 = s0 - __bfloat162float(h0);
                float l1 = s1 - __bfloat162float(h1);
                unsigned hp = (unsigned)__bfloat16_as_ushort(h0) |
                              ((unsigned)__bfloat16_as_ushort(h1) << 16);
                unsigned lp = (unsigned)__bfloat16_as_ushort(__float2bfloat16_rn(l0)) |
                              ((unsigned)__bfloat16_as_ushort(__float2bfloat16_rn(l1)) << 16);
                size_t qo = (((size_t)(b * HH + h)) * TT + t) * 32 + (d >> 1);
                if (z == 0) { g_Qh[qo] = hp; g_Ql[qo] = lp; }
                else        { g_Kh[qo] = hp; g_Kl[qo] = lp; }
            }
        }
    }
}

// ---------------------------------------------------------------------------
// KL statistic: base-2 online softmax, split-K (zk=2), Q fragments loaded
// directly from gmem (no Q smem). smem: 2 K stages x 32KB = 64KB.
// grid (qt=16, bh=16, zk=2), 256 thr.
// ---------------------------------------------------------------------------
__global__ __launch_bounds__(256, 2) void kl_mma_kernel() {
    extern __shared__ char dsm[];
    char* sbase = (char*)(((uintptr_t)dsm + 1023u) & ~(uintptr_t)1023u);
    const uint32_t sb = smem_u32(sbase);

    const int tid = threadIdx.x;
    const int wid = tid >> 5, lane = tid & 31;
    const int r = lane & 7, g = lane >> 3;
    const int wrow0 = wid * 16;
    const int bh = blockIdx.y;
    const int q0 = blockIdx.x * 128;
    const int zk = blockIdx.z;

    auto prefetchK = [&](int ktl) {
        uint32_t stg = sb + (ktl & 1) * 32768;
        int ktg = zk * 8 + ktl;
#pragma unroll
        for (int j = 0; j < 4; j++) {
            int i = tid + j * 256;
            int row = i >> 3, c = i & 7;
            uint32_t boff = row * 128 + c * 16;
            uint32_t swb = boff ^ ((boff >> 3) & 0x70);
            size_t sidx = (size_t)(bh * TT + ktg * 128 + row) * 8 + c;
            CP_ASYNC16(stg + swb,         (const uint4*)g_Kh + sidx);
            CP_ASYNC16(stg + 16384 + swb, (const uint4*)g_Kl + sidx);
        }
    };

    prefetchK(0); CP_COMMIT();

    // Q fragments straight from gmem per the m16n8k16 A-fragment spec:
    // a0: row (lane>>2), k pair (lane&3); a1: row+8; a2: k+8; a3: row+8,k+8
    uint32_t Ah[4][4], Al[4][4];
    {
        const int row0 = q0 + wrow0 + (lane >> 2);
        const size_t qb0 = ((size_t)bh * TT + row0) * 32;
        const size_t qb1 = qb0 + 8 * 32;
#pragma unroll
        for (int ks = 0; ks < 4; ks++) {
            int cu = ks * 8 + (lane & 3);
            Ah[ks][0] = g_Qh[qb0 + cu];
            Ah[ks][1] = g_Qh[qb1 + cu];
            Ah[ks][2] = g_Qh[qb0 + cu + 4];
            Ah[ks][3] = g_Qh[qb1 + cu + 4];
            Al[ks][0] = g_Ql[qb0 + cu];
            Al[ks][1] = g_Ql[qb1 + cu];
            Al[ks][2] = g_Ql[qb0 + cu + 4];
            Al[ks][3] = g_Ql[qb1 + cu + 4];
        }
    }

    float mst[2] = {-1e30f, -1e30f}, Zc[2] = {0.f, 0.f}, Tc[2] = {0.f, 0.f};
    const int gbB = g & 1;
    const int rowBoff = r + ((g >> 1) & 1) * 8;

    for (int ktl = 0; ktl < 8; ktl++) {
        if (ktl < 7) { prefetchK(ktl + 1); CP_COMMIT(); CP_WAIT1(); }
        else CP_WAIT0();
        __syncthreads();
        const uint32_t stg = sb + (ktl & 1) * 32768;

        float acc[16][4];
#pragma unroll
        for (int i = 0; i < 16; i++)
#pragma unroll
            for (int j = 0; j < 4; j++) acc[i][j] = 0.f;

#pragma unroll
        for (int ks = 0; ks < 4; ks++) {
            uint32_t boffs = ((uint32_t)((ks * 2 + gbB) * 16)) ^ (uint32_t)(r * 16);
#pragma unroll
            for (int np = 0; np < 8; np++) {
                uint32_t bbase = stg + (np * 16 + rowBoff) * 128 + boffs;
                uint32_t bh0, bh1, bh2, bh3, bl0, bl1, bl2, bl3;
                ldsm4(bbase, bh0, bh1, bh2, bh3);
                ldsm4(bbase + 16384, bl0, bl1, bl2, bl3);
                int f0 = np * 2, f1 = np * 2 + 1;
                mma_bf16(acc[f0][0], acc[f0][1], acc[f0][2], acc[f0][3],
                         Ah[ks][0], Ah[ks][1], Ah[ks][2], Ah[ks][3], bh0, bh1);
                mma_bf16(acc[f1][0], acc[f1][1], acc[f1][2], acc[f1][3],
                         Ah[ks][0], Ah[ks][1], Ah[ks][2], Ah[ks][3], bh2, bh3);
                mma_bf16(acc[f0][0], acc[f0][1], acc[f0][2], acc[f0][3],
                         Ah[ks][0], Ah[ks][1], Ah[ks][2], Ah[ks][3], bl0, bl1);
                mma_bf16(acc[f1][0], acc[f1][1], acc[f1][2], acc[f1][3],
                         Ah[ks][0], Ah[ks][1], Ah[ks][2], Ah[ks][3], bl2, bl3);
                mma_bf16(acc[f0][0], acc[f0][1], acc[f0][2], acc[f0][3],
                         Al[ks][0], Al[ks][1], Al[ks][2], Al[ks][3], bh0, bh1);
                mma_bf16(acc[f1][0], acc[f1][1], acc[f1][2], acc[f1][3],
                         Al[ks][0], Al[ks][1], Al[ks][2], Al[ks][3], bh2, bh3);
            }
        }

        // base-2 online softmax/KL update; scores already in log2 domain
#pragma unroll
        for (int h2 = 0; h2 < 2; h2++) {
            float tmax = -1e30f;
#pragma unroll
            for (int nf = 0; nf < 16; nf++)
                tmax = fmaxf(tmax, fmaxf(acc[nf][h2 * 2], acc[nf][h2 * 2 + 1]));
            float nm = fmaxf(mst[h2], tmax);
            float f = ex2f(mst[h2] - nm);
            float zs = 0.f, ts = 0.f;
#pragma unroll
            for (int nf = 0; nf < 16; nf++) {
                float u0 = acc[nf][h2 * 2];
                float u1 = acc[nf][h2 * 2 + 1];
                float e0 = ex2f(u0 - nm);
                float e1 = ex2f(u1 - nm);
                zs += e0 + e1;
                ts = fmaf(e0, u0, ts);
                ts = fmaf(e1, u1, ts);
            }
            Zc[h2] = Zc[h2] * f + zs;
            Tc[h2] = Tc[h2] * f + ts;
            mst[h2] = nm;
        }
        __syncthreads();
    }

    // merge across the 4 lanes sharing each row, then store split-K partials
#pragma unroll
    for (int h2 = 0; h2 < 2; h2++) {
#pragma unroll
        for (int off = 1; off < 4; off <<= 1) {
            float mo = __shfl_xor_sync(0xffffffffu, mst[h2], off, 4);
            float zo = __shfl_xor_sync(0xffffffffu, Zc[h2],  off, 4);
            float to = __shfl_xor_sync(0xffffffffu, Tc[h2],  off, 4);
            float nm = fmaxf(mst[h2], mo);
            float f1 = ex2f(mst[h2] - nm), f2 = ex2f(mo - nm);
            Zc[h2] = Zc[h2] * f1 + zo * f2;
            Tc[h2] = Tc[h2] * f1 + to * f2;
            mst[h2] = nm;
        }
        if ((lane & 3) == 0) {
            int q = q0 + wrow0 + (lane >> 2) + h2 * 8;
            size_t o = ((size_t)zk * BH * TT + (size_t)bh * TT + q) * 4;
            *(float4*)&g_kp[o] = make_float4(mst[h2], Zc[h2], Tc[h2], 0.f);
        }
    }
}

// merge the two K-halves into the final KL statistic
__global__ __launch_bounds__(256) void kl_merge_kernel() {
    int idx = blockIdx.x * 256 + threadIdx.x;   // over BH*TT
    float4 p0 = *(float4*)&g_kp[(size_t)idx * 4];
    float4 p1 = *(float4*)&g_kp[((size_t)BH * TT + idx) * 4];
    float nm = fmaxf(p0.x, p1.x);
    float f0 = ex2f(p0.x - nm), f1 = ex2f(p1.x - nm);
    float Z = p0.y * f0 + p1.y * f1;
    float T = p0.z * f0 + p1.z * f1;
    g_kl[idx] = 0.6931471805599453f * (T / Z - nm - log2f(Z));
}

// ---------------------------------------------------------------------------
// Top-3 per (b,h) by KL (jax tie semantics: lower index wins)
// ---------------------------------------------------------------------------
__global__ void top3_kernel() {
    const int bh = blockIdx.x;
    __shared__ float sv[256];
    __shared__ int   si[256];
    __shared__ int   chosen[UU];
    const float* kl = g_kl + (size_t)bh * TT;
    for (int p = 0; p < UU; p++) {
        float bv = -1e38f; int bi = TT;
        for (int q = threadIdx.x; q < TT; q += 256) {
            bool skip = false;
            for (int c = 0; c < p; c++) if (chosen[c] == q) skip = true;
            if (skip) continue;
            float v = kl[q];
            if (v > bv || (v == bv && q < bi)) { bv = v; bi = q; }
        }
        sv[threadIdx.x] = bv; si[threadIdx.x] = bi;
        __syncthreads();
        for (int s = 128; s > 0; s >>= 1) {
            if (threadIdx.x < s) {
                float ov = sv[threadIdx.x + s]; int oi = si[threadIdx.x + s];
                if (ov > sv[threadIdx.x] ||
                    (ov == sv[threadIdx.x] && oi < si[threadIdx.x])) {
                    sv[threadIdx.x] = ov; si[threadIdx.x] = oi;
                }
            }
            __syncthreads();
        }
        if (threadIdx.x == 0) { chosen[p] = si[0]; g_top[bh * UU + p] = si[0]; }
        __syncthreads();
    }
}

// ---------------------------------------------------------------------------
// Reduced attention, split-K: grid (48 slots, 8 parts), 256 keys per part.
// ---------------------------------------------------------------------------
__global__ __launch_bounds__(256) void redattn_part_kernel() {
    const int slot = blockIdx.x;
    const int part = blockIdx.y;
    const int bh = slot / UU;
    const int t = g_top[slot];
    __shared__ float qrow[64];
    __shared__ float sarr[256];
    __shared__ float red[256];
    const int tid = threadIdx.x;

    if (tid < 64) qrow[tid] = g_Q[((size_t)bh * TT + t) * DD + tid];
    __syncthreads();

    const int k = part * 256 + tid;
    {
        const float* kr = g_K + ((size_t)bh * TT + k) * DD;
        float s = 0.f;
#pragma unroll
        for (int d = 0; d < 64; d++) s = fmaf(qrow[d], kr[d], s);
        s *= 0.125f;
        if (!(s == s)) s = -10000.0f;
        s = fminf(fmaxf(s, -10000.0f), 10000.0f);
        sarr[tid] = s;
        red[tid] = s;
    }
    __syncthreads();
    for (int s = 128; s > 0; s >>= 1) {
        if (tid < s) red[tid] = fmaxf(red[tid], red[tid + s]);
        __syncthreads();
    }
    const float mx = red[0];
    __syncthreads();

    float e = expf(sarr[tid] - mx);
    sarr[tid] = e;
    red[tid] = e;
    __syncthreads();
    for (int s = 128; s > 0; s >>= 1) {
        if (tid < s) red[tid] += red[tid + s];
        __syncthreads();
    }
    const float Zp = red[0];
    __syncthreads();

    const int d = tid % 64, gi = tid / 64;
    float acc = 0.f;
    for (int kk = gi; kk < 256; kk += 4)
        acc = fmaf(sarr[kk], g_V[((size_t)bh * TT + part * 256 + kk) * DD + d], acc);
    red[tid] = acc; __syncthreads();

    float* pp = g_part + (size_t)(slot * 8 + part) * 68;
    if (tid == 0) { pp[0] = mx; pp[1] = Zp; }
    if (tid < 64)
        pp[2 + tid] = red[tid] + red[tid + 64] + red[tid + 128] + red[tid + 192];
}

__global__ void redattn_combine_kernel() {
    const int slot = blockIdx.x;
    const int d = threadIdx.x;   // 64 threads
    float mstar = -1e30f;
#pragma unroll
    for (int p = 0; p < 8; p++)
        mstar = fmaxf(mstar, g_part[(size_t)(slot * 8 + p) * 68]);
    float Z = 0.f, acc = 0.f;
#pragma unroll
    for (int p = 0; p < 8; p++) {
        const float* pp = g_part + (size_t)(slot * 8 + p) * 68;
        float f = expf(pp[0] - mstar);
        Z += pp[1] * f;
        acc += pp[2 + d] * f;
    }
    g_or[(size_t)slot * DD + d] = acc / Z;
}

// ---------------------------------------------------------------------------
// Output: init to bias, then sparse-project the 48 nonzero rows with Wo
// ---------------------------------------------------------------------------
__global__ void init_out_kernel(float* __restrict__ out, const float* __restrict__ bo) {
    int idx = blockIdx.x * 256 + threadIdx.x;
    if (idx < BB * TT * DMM) out[idx] = bo[idx % DMM];
}

__global__ void scatter_kernel(const float* __restrict__ Wo, float* __restrict__ out) {
    const int slot = blockIdx.x;
    const int bh = slot / UU;
    const int b = bh / HH, h = bh % HH;
    const int t = g_top[slot];
    __shared__ float orow[64];
    if (threadIdx.x < 64) orow[threadIdx.x] = g_or[(size_t)slot * DD + threadIdx.x];
    __syncthreads();
    for (int n = threadIdx.x; n < DMM; n += 256) {
        const float* wr = Wo + (size_t)n * DMM + h * DD;
        float acc = 0.f;
#pragma unroll
        for (int d = 0; d < 64; d++) acc = fmaf(orow[d], wr[d], acc);
        atomicAdd(&out[((size_t)b * TT + t) * DMM + n], acc);
    }
}

// ---------------------------------------------------------------------------
extern "C" void kernel_launch(void* const* d_in, const int* in_sizes, int n_in,
                              void* d_out, int out_size) {
    const float* query = (const float*)d_in[0];
    const float* key   = (const float*)d_in[1];
    const float* value = (const float*)d_in[2];
    const float* Wq = (const float*)d_in[3];
    const float* bq = (const float*)d_in[4];
    const float* Wk = (const float*)d_in[5];
    const float* bk = (const float*)d_in[6];
    const float* Wv = (const float*)d_in[7];
    const float* bv = (const float*)d_in[8];
    const float* Wo = (const float*)d_in[9];
    const float* bo = (const float*)d_in[10];
    float* out = (float*)d_out;

    float *Qp, *Kp, *Vp;
    cudaGetSymbolAddress((void**)&Qp, g_Q);
    cudaGetSymbolAddress((void**)&Kp, g_K);
    cudaGetSymbolAddress((void**)&Vp, g_V);

    const int proj_smem = 65536 + 1024;
    const int kl_smem   = 65536 + 1024;
    cudaFuncSetAttribute(proj_mma_kernel, cudaFuncAttributeMaxDynamicSharedMemorySize, proj_smem);
    cudaFuncSetAttribute(kl_mma_kernel,   cudaFuncAttributeMaxDynamicSharedMemorySize, kl_smem);

    convx_kernel<<<dim3(1024, 3), 256>>>(query, key, value);
    convw_kernel<<<dim3(128, 3), 256>>>(Wq, Wk, Wv);

    proj_mma_kernel<<<dim3(4, 32, 3), 256, proj_smem>>>(bq, bk, bv, Qp, Kp, Vp);

    kl_mma_kernel<<<dim3(16, 16, 2), 256, kl_smem>>>();
    kl_merge_kernel<<<(BH * TT) / 256, 256>>>();

    top3_kernel<<<BH, 256>>>();
    redattn_part_kernel<<<dim3(BH * UU, 8), 256>>>();
    redattn_combine_kernel<<<BH * UU, 64>>>();

    init_out_kernel<<<(BB * TT * DMM + 255) / 256, 256>>>(out, bo);
    scatter_kernel<<<BH * UU, 256>>>(Wo, out);
}